// round 7
// baseline (speedup 1.0000x reference)
#include <cuda_runtime.h>
#include <cuda_bf16.h>
#include <math_constants.h>

#define NN 100000
#define EE 1600000
#define F_IN 256
#define HH 4
#define DD 32
#define CC 47
#define NEG_SLOPE 0.2f

#define BM 128
#define BK 16

// ---------------- scratch (__device__ globals; no allocation) ----------------
__device__ float g_feat [NN * HH * CC];   // gemm output [N, H*od] (max 188 wide)
__device__ float g_out  [NN * HH * CC];   // aggregated output / next-layer input
__device__ float g_el   [NN * HH];        // [N,4] -> float4 per node
__device__ float g_er   [NN * HH];
__device__ float g_inv  [NN * HH];        // 1/den per (node, head)
__device__ float g_alpha[EE * HH];        // CSR-ordered ex per (pos, head)
__device__ int   g_deg  [NN];
__device__ int   g_cnt  [NN];             // scatter cursor (init = rowptr)
__device__ int   g_rowptr[NN + 1];
__device__ int   g_csrc [EE];             // src node per CSR position

// ====================== CSR build (once per launch) ======================
__global__ void __launch_bounds__(256)
zero_deg_kernel() {
    int i = blockIdx.x * blockDim.x + threadIdx.x;
    if (i < NN) g_deg[i] = 0;
}

__global__ void __launch_bounds__(256)
hist_kernel(const int* __restrict__ dst) {
    int e = blockIdx.x * blockDim.x + threadIdx.x;
    if (e < EE) atomicAdd(&g_deg[dst[e]], 1);
}

// single-block exclusive scan of g_deg -> g_rowptr (and g_cnt = rowptr copy)
__global__ void __launch_bounds__(1024)
scan_kernel() {
    __shared__ int sh[1024];
    const int t = threadIdx.x;
    const int CH = (NN + 1023) / 1024;   // 98
    const int base = t * CH;
    int sum = 0;
    #pragma unroll 1
    for (int i = 0; i < CH; i++) {
        int idx = base + i;
        if (idx < NN) sum += g_deg[idx];
    }
    sh[t] = sum;
    __syncthreads();
    for (int o = 1; o < 1024; o <<= 1) {
        int v = (t >= o) ? sh[t - o] : 0;
        __syncthreads();
        sh[t] += v;
        __syncthreads();
    }
    int excl = (t == 0) ? 0 : sh[t - 1];
    #pragma unroll 1
    for (int i = 0; i < CH; i++) {
        int idx = base + i;
        if (idx < NN) {
            g_rowptr[idx] = excl;
            g_cnt[idx] = excl;
            excl += g_deg[idx];
        }
    }
    if (t == 1023) g_rowptr[NN] = sh[1023];
}

__global__ void __launch_bounds__(256)
scatter_kernel(const int* __restrict__ src, const int* __restrict__ dst) {
    int e = blockIdx.x * blockDim.x + threadIdx.x;
    if (e >= EE) return;
    int p = atomicAdd(&g_cnt[dst[e]], 1);
    g_csrc[p] = src[e];
}

// ====================== SGEMM: g_feat[M,N] = A[M,K] @ B[K,N] ======================
// BMx(TBN) tile, BK=16, 256 threads, 8x(TBN/16) per thread, double-buffered, FFMA2.
template<int TBN>
__device__ __forceinline__ void load_tile(
    const float* __restrict__ A, const float* __restrict__ B,
    int M, int N, int K, int row0, int col0, int k0, int tid,
    float (* __restrict__ As)[BM + 2], float (* __restrict__ Bs)[TBN]) {
    #pragma unroll
    for (int t = 0; t < 2; t++) {
        // A tile: 128 rows x 16 k, transposed into As[k][m]
        int fi = tid + t * 256;
        int row = fi >> 2, kq = fi & 3;
        int gr = row0 + row;
        float4 v = make_float4(0.f, 0.f, 0.f, 0.f);
        if (gr < M) v = *(const float4*)&A[(long)gr * K + k0 + kq * 4];
        As[kq * 4 + 0][row] = v.x;
        As[kq * 4 + 1][row] = v.y;
        As[kq * 4 + 2][row] = v.z;
        As[kq * 4 + 3][row] = v.w;
    }
    #pragma unroll
    for (int t = 0; t < TBN / 64; t++) {
        // B tile: 16 k x TBN cols
        int fi = tid + t * 256;
        int krow = fi / (TBN / 4), nq = fi % (TBN / 4);
        int gc = col0 + nq * 4;
        float4 v = make_float4(0.f, 0.f, 0.f, 0.f);
        if (gc < N) v = *(const float4*)&B[(long)(k0 + krow) * N + gc];
        *(float4*)&Bs[krow][nq * 4] = v;
    }
}

template<int TBN>
__global__ void __launch_bounds__(256, 2)
sgemm_kernel(const float* __restrict__ A, const float* __restrict__ B,
             int M, int N, int K) {
    constexpr int CPT = TBN / 16;          // cols per thread (8 or 4)
    __shared__ __align__(16) float As[2][BK][BM + 2];
    __shared__ __align__(16) float Bs[2][BK][TBN];
    const int tid = threadIdx.x;
    const int tx = tid & 15;
    const int ty = tid >> 4;
    const int row0 = blockIdx.x * BM;
    const int col0 = blockIdx.y * TBN;

    unsigned long long acc[4][CPT];
    #pragma unroll
    for (int r = 0; r < 4; r++)
        #pragma unroll
        for (int j = 0; j < CPT; j++) acc[r][j] = 0ull;

    load_tile<TBN>(A, B, M, N, K, row0, col0, 0, tid, As[0], Bs[0]);
    __syncthreads();

    int buf = 0;
    for (int k0 = 0; k0 < K; k0 += BK) {
        if (k0 + BK < K)
            load_tile<TBN>(A, B, M, N, K, row0, col0, k0 + BK, tid, As[buf ^ 1], Bs[buf ^ 1]);
        #pragma unroll
        for (int kk = 0; kk < BK; kk++) {
            unsigned long long ap[4];
            #pragma unroll
            for (int r = 0; r < 4; r++)
                ap[r] = *(const unsigned long long*)&As[buf][kk][ty * 8 + r * 2];
            unsigned long long bd[CPT];
            #pragma unroll
            for (int j = 0; j < CPT; j++) {
                float bv = Bs[buf][kk][tx * CPT + j];
                asm("mov.b64 %0, {%1, %1};" : "=l"(bd[j]) : "f"(bv));
            }
            #pragma unroll
            for (int r = 0; r < 4; r++)
                #pragma unroll
                for (int j = 0; j < CPT; j++)
                    asm("fma.rn.f32x2 %0, %1, %2, %0;"
                        : "+l"(acc[r][j]) : "l"(ap[r]), "l"(bd[j]));
        }
        __syncthreads();
        buf ^= 1;
    }

    const int cbase = col0 + tx * CPT;
    #pragma unroll
    for (int r = 0; r < 4; r++) {
        float lo[CPT], hi[CPT];
        #pragma unroll
        for (int j = 0; j < CPT; j++)
            asm("mov.b64 {%0, %1}, %2;" : "=f"(lo[j]), "=f"(hi[j]) : "l"(acc[r][j]));
        int gr0 = row0 + ty * 8 + 2 * r;
        #pragma unroll
        for (int p = 0; p < 2; p++) {
            int gr = gr0 + p;
            if (gr >= M) continue;
            const float* c = p ? hi : lo;
            if (cbase + CPT - 1 < N) {
                #pragma unroll
                for (int q = 0; q < CPT / 4; q++)
                    *(float4*)&g_feat[(long)gr * N + cbase + q * 4] =
                        make_float4(c[q * 4], c[q * 4 + 1], c[q * 4 + 2], c[q * 4 + 3]);
            } else {
                for (int jj = 0; jj < CPT; jj++)
                    if (cbase + jj < N) g_feat[(long)gr * N + cbase + jj] = c[jj];
            }
        }
    }
}

// ====================== el/er per (node, head) ======================
__global__ void __launch_bounds__(256)
elr_kernel(const float* __restrict__ al, const float* __restrict__ ar, int od) {
    int idx = blockIdx.x * blockDim.x + threadIdx.x;   // n*H + h
    if (idx >= NN * HH) return;
    int n = idx >> 2, h = idx & 3;
    const float* f = g_feat + (long)n * HH * od + h * od;
    const float* alh = al + h * od;
    const float* arh = ar + h * od;
    float sl = 0.f, sr = 0.f;
    for (int d = 0; d < od; d++) { float v = f[d]; sl += v * alh[d]; sr += v * arh[d]; }
    g_el[idx] = sl;
    g_er[idx] = sr;
}

// ====================== two-pass edge softmax (warp per node) ======================
// Pass 1 gathers el (no store); pass 2 recomputes e, stores ex, computes inv.
__device__ __forceinline__ float lrelu(float v) { return v > 0.f ? v : NEG_SLOPE * v; }

__global__ void __launch_bounds__(256)
attn_softmax_kernel() {
    int node = (blockIdx.x * blockDim.x + threadIdx.x) >> 5;
    int lane = threadIdx.x & 31;
    if (node >= NN) return;
    int r0 = g_rowptr[node], r1 = g_rowptr[node + 1];

    float4 erd = *(const float4*)&g_er[node * 4];

    // pass 1: per-head max (independent iterations)
    float mx0 = -CUDART_INF_F, mx1 = -CUDART_INF_F, mx2 = -CUDART_INF_F, mx3 = -CUDART_INF_F;
    for (int i = r0 + lane; i < r1; i += 32) {
        int s = g_csrc[i];
        float4 ev = *(const float4*)&g_el[s * 4];
        mx0 = fmaxf(mx0, lrelu(ev.x + erd.x));
        mx1 = fmaxf(mx1, lrelu(ev.y + erd.y));
        mx2 = fmaxf(mx2, lrelu(ev.z + erd.z));
        mx3 = fmaxf(mx3, lrelu(ev.w + erd.w));
    }
    #pragma unroll
    for (int o = 16; o > 0; o >>= 1) {
        mx0 = fmaxf(mx0, __shfl_xor_sync(0xffffffffu, mx0, o));
        mx1 = fmaxf(mx1, __shfl_xor_sync(0xffffffffu, mx1, o));
        mx2 = fmaxf(mx2, __shfl_xor_sync(0xffffffffu, mx2, o));
        mx3 = fmaxf(mx3, __shfl_xor_sync(0xffffffffu, mx3, o));
    }

    // pass 2: recompute e (el gather is L2-hot), ex = exp(e - m); store; sum
    float s0 = 0.f, s1 = 0.f, s2 = 0.f, s3 = 0.f;
    for (int i = r0 + lane; i < r1; i += 32) {
        int s = g_csrc[i];
        float4 ev = *(const float4*)&g_el[s * 4];
        float4 e;
        e.x = __expf(lrelu(ev.x + erd.x) - mx0);
        e.y = __expf(lrelu(ev.y + erd.y) - mx1);
        e.z = __expf(lrelu(ev.z + erd.z) - mx2);
        e.w = __expf(lrelu(ev.w + erd.w) - mx3);
        *(float4*)&g_alpha[i * 4] = e;
        s0 += e.x; s1 += e.y; s2 += e.z; s3 += e.w;
    }
    #pragma unroll
    for (int o = 16; o > 0; o >>= 1) {
        s0 += __shfl_xor_sync(0xffffffffu, s0, o);
        s1 += __shfl_xor_sync(0xffffffffu, s1, o);
        s2 += __shfl_xor_sync(0xffffffffu, s2, o);
        s3 += __shfl_xor_sync(0xffffffffu, s3, o);
    }
    if (lane == 0)
        *(float4*)&g_inv[node * 4] = make_float4(1.f / s0, 1.f / s1, 1.f / s2, 1.f / s3);
}

__device__ __forceinline__ float pick4(float4 v, int h) {
    float ab = (h & 1) ? v.y : v.x;
    float cd = (h & 1) ? v.w : v.z;
    return (h & 2) ? cd : ab;
}

// ====================== aggregation F=128 (warp per node, atomic-free) ======================
// lane owns features [lane*4, lane*4+4); head = lane>>3. alpha = ex*inv. bias+relu fused.
__global__ void __launch_bounds__(256)
agg128_kernel(const float* __restrict__ bias) {
    int node = (blockIdx.x * blockDim.x + threadIdx.x) >> 5;
    int lane = threadIdx.x & 31;
    if (node >= NN) return;
    int r0 = g_rowptr[node], r1 = g_rowptr[node + 1];
    const int head = lane >> 3;

    float invh = pick4(*(const float4*)&g_inv[node * 4], head);

    float4 acc = {0.f, 0.f, 0.f, 0.f};
    int i = r0;
    #pragma unroll 1
    for (; i + 7 < r1; i += 8) {
        int s[8];
        #pragma unroll
        for (int k = 0; k < 8; k++) s[k] = g_csrc[i + k];
        float a[8];
        #pragma unroll
        for (int k = 0; k < 8; k++) a[k] = g_alpha[(long)(i + k) * 4 + head] * invh;
        float4 f[8];
        #pragma unroll
        for (int k = 0; k < 8; k++)
            f[k] = *(const float4*)&g_feat[(long)s[k] * 128 + lane * 4];
        #pragma unroll
        for (int k = 0; k < 8; k++) {
            acc.x += a[k] * f[k].x;
            acc.y += a[k] * f[k].y;
            acc.z += a[k] * f[k].z;
            acc.w += a[k] * f[k].w;
        }
    }
    for (; i < r1; i++) {
        int s = g_csrc[i];
        float a = g_alpha[(long)i * 4 + head] * invh;
        float4 f = *(const float4*)&g_feat[(long)s * 128 + lane * 4];
        acc.x += a * f.x; acc.y += a * f.y; acc.z += a * f.z; acc.w += a * f.w;
    }
    float4 b = *(const float4*)&bias[lane * 4];
    acc.x = fmaxf(acc.x + b.x, 0.f);
    acc.y = fmaxf(acc.y + b.y, 0.f);
    acc.z = fmaxf(acc.z + b.z, 0.f);
    acc.w = fmaxf(acc.w + b.w, 0.f);
    *(float4*)&g_out[(long)node * 128 + lane * 4] = acc;
}

// ====================== aggregation F=188 (warp per node; no bias/act) ======================
__global__ void __launch_bounds__(256)
agg188_kernel() {
    int node = (blockIdx.x * blockDim.x + threadIdx.x) >> 5;
    int lane = threadIdx.x & 31;
    if (node >= NN) return;
    int r0 = g_rowptr[node], r1 = g_rowptr[node + 1];

    float4 inv4 = *(const float4*)&g_inv[node * 4];

    float acc[6] = {0.f, 0.f, 0.f, 0.f, 0.f, 0.f};
    int headk[6];
    #pragma unroll
    for (int k = 0; k < 6; k++) headk[k] = (lane + 32 * k) / CC;  // feature/47

    for (int i = r0; i < r1; i++) {
        int s = g_csrc[i];
        float4 e4 = *(const float4*)&g_alpha[(long)i * 4];
        float4 av = make_float4(e4.x * inv4.x, e4.y * inv4.y,
                                e4.z * inv4.z, e4.w * inv4.w);
        const float* fs = g_feat + (long)s * 188;
        #pragma unroll
        for (int k = 0; k < 6; k++) {
            int j = lane + 32 * k;
            if (j < 188) acc[k] += pick4(av, headk[k]) * fs[j];
        }
    }
    float* op = g_out + (long)node * 188;
    #pragma unroll
    for (int k = 0; k < 6; k++) {
        int j = lane + 32 * k;
        if (j < 188) op[j] = acc[k];
    }
}

// ====================== final: head-mean (+bias) + log_softmax (warp per node) ======================
__global__ void __launch_bounds__(256)
final_kernel(const float* __restrict__ b3, float* __restrict__ y) {
    int node = (blockIdx.x * blockDim.x + threadIdx.x) >> 5;
    int lane = threadIdx.x & 31;
    if (node >= NN) return;
    const float* row = g_out + (long)node * HH * CC;

    float a0 = 0.f, a1 = 0.f;
    float v0 = -CUDART_INF_F, v1 = -CUDART_INF_F;
    if (lane < CC) {
        float sum = 0.f;
        #pragma unroll
        for (int h = 0; h < HH; h++) sum += row[h * CC + lane] + b3[h * CC + lane];
        a0 = sum * 0.25f; v0 = a0;
    }
    int c1 = lane + 32;
    if (c1 < CC) {
        float sum = 0.f;
        #pragma unroll
        for (int h = 0; h < HH; h++) sum += row[h * CC + c1] + b3[h * CC + c1];
        a1 = sum * 0.25f; v1 = a1;
    }
    float mx = fmaxf(v0, v1);
    #pragma unroll
    for (int o = 16; o > 0; o >>= 1) mx = fmaxf(mx, __shfl_xor_sync(0xffffffffu, mx, o));
    float s = 0.f;
    if (lane < CC) s += __expf(a0 - mx);
    if (c1 < CC)   s += __expf(a1 - mx);
    #pragma unroll
    for (int o = 16; o > 0; o >>= 1) s += __shfl_xor_sync(0xffffffffu, s, o);
    float lse = logf(s);
    if (lane < CC) y[(long)node * CC + lane] = a0 - mx - lse;
    if (c1 < CC)   y[(long)node * CC + c1] = a1 - mx - lse;
}

// ====================== host driver ======================
extern "C" void kernel_launch(void* const* d_in, const int* in_sizes, int n_in,
                              void* d_out, int out_size) {
    const float* x   = (const float*)d_in[0];
    const int*   src = (const int*)  d_in[1];
    const int*   dst = (const int*)  d_in[2];
    const float* W1  = (const float*)d_in[3];
    const float* al1 = (const float*)d_in[4];
    const float* ar1 = (const float*)d_in[5];
    const float* b1  = (const float*)d_in[6];
    const float* W2  = (const float*)d_in[7];
    const float* al2 = (const float*)d_in[8];
    const float* ar2 = (const float*)d_in[9];
    const float* b2  = (const float*)d_in[10];
    const float* W3  = (const float*)d_in[11];
    const float* al3 = (const float*)d_in[12];
    const float* ar3 = (const float*)d_in[13];
    const float* b3  = (const float*)d_in[14];
    float* y = (float*)d_out;

    static float* outb = nullptr;
    if (!outb) cudaGetSymbolAddress((void**)&outb, g_out);

    const int TB = 256;
    const int nodeWarpGrid = (NN + 7) / 8;

    // ---- CSR build (graph static across layers) ----
    zero_deg_kernel<<<(NN + TB - 1) / TB, TB>>>();
    hist_kernel<<<(EE + TB - 1) / TB, TB>>>(dst);
    scan_kernel<<<1, 1024>>>();
    scatter_kernel<<<(EE + TB - 1) / TB, TB>>>(src, dst);

    // ---- layer 1: x [N,256] -> g_out [N,128] ----
    {
        dim3 gg((NN + BM - 1) / BM, 1);
        sgemm_kernel<128><<<gg, TB>>>(x, W1, NN, 128, F_IN);
        elr_kernel<<<(NN * HH + TB - 1) / TB, TB>>>(al1, ar1, DD);
        attn_softmax_kernel<<<nodeWarpGrid, TB>>>();
        agg128_kernel<<<nodeWarpGrid, TB>>>(b1);
    }
    // ---- layer 2: g_out [N,128] -> g_out [N,128] ----
    {
        dim3 gg((NN + BM - 1) / BM, 1);
        sgemm_kernel<128><<<gg, TB>>>(outb, W2, NN, 128, 128);
        elr_kernel<<<(NN * HH + TB - 1) / TB, TB>>>(al2, ar2, DD);
        attn_softmax_kernel<<<nodeWarpGrid, TB>>>();
        agg128_kernel<<<nodeWarpGrid, TB>>>(b2);
    }
    // ---- layer 3: g_out [N,128] -> g_out [N,188] (BN=64 tiles; bias fused into final) ----
    {
        dim3 gg((NN + BM - 1) / BM, (188 + 63) / 64);
        sgemm_kernel<64><<<gg, TB>>>(outb, W3, NN, 188, 128);
        elr_kernel<<<(NN * HH + TB - 1) / TB, TB>>>(al3, ar3, CC);
        attn_softmax_kernel<<<nodeWarpGrid, TB>>>();
        agg188_kernel<<<nodeWarpGrid, TB>>>();
    }
    // ---- head-mean + bias + log_softmax ----
    final_kernel<<<(NN + 7) / 8, TB>>>(b3, y);
}

// round 8
// speedup vs baseline: 1.1338x; 1.1338x over previous
#include <cuda_runtime.h>
#include <cuda_bf16.h>
#include <math_constants.h>

#define NN 100000
#define EE 1600000
#define F_IN 256
#define HH 4
#define DD 32
#define CC 47
#define NEG_SLOPE 0.2f

#define BM 128
#define BK 16

// ---------------- scratch (__device__ globals; no allocation) ----------------
__device__ float g_feat [NN * HH * CC];   // gemm output [N, H*od] (max 188 wide)
__device__ float g_out  [NN * HH * CC];   // aggregated output / next-layer input
__device__ float g_el   [NN * HH];        // [N,4] -> float4 per node
__device__ float g_er   [NN * HH];
__device__ int   g_deg  [NN];
__device__ int   g_cnt  [NN];             // scatter cursor (init = rowptr)
__device__ int   g_rowptr[NN + 1];
__device__ int   g_csrc [EE];             // src node per CSR position

// ====================== CSR build (once per launch) ======================
__global__ void __launch_bounds__(256)
zero_deg_kernel() {
    int i = blockIdx.x * blockDim.x + threadIdx.x;
    if (i < NN) g_deg[i] = 0;
}

__global__ void __launch_bounds__(256)
hist_kernel(const int* __restrict__ dst) {
    int e = blockIdx.x * blockDim.x + threadIdx.x;
    if (e < EE) atomicAdd(&g_deg[dst[e]], 1);
}

// single-block exclusive scan of g_deg -> g_rowptr (and g_cnt = rowptr copy)
__global__ void __launch_bounds__(1024)
scan_kernel() {
    __shared__ int sh[1024];
    const int t = threadIdx.x;
    const int CH = (NN + 1023) / 1024;   // 98
    const int base = t * CH;
    int sum = 0;
    #pragma unroll 1
    for (int i = 0; i < CH; i++) {
        int idx = base + i;
        if (idx < NN) sum += g_deg[idx];
    }
    sh[t] = sum;
    __syncthreads();
    for (int o = 1; o < 1024; o <<= 1) {
        int v = (t >= o) ? sh[t - o] : 0;
        __syncthreads();
        sh[t] += v;
        __syncthreads();
    }
    int excl = (t == 0) ? 0 : sh[t - 1];
    #pragma unroll 1
    for (int i = 0; i < CH; i++) {
        int idx = base + i;
        if (idx < NN) {
            g_rowptr[idx] = excl;
            g_cnt[idx] = excl;
            excl += g_deg[idx];
        }
    }
    if (t == 1023) g_rowptr[NN] = sh[1023];
}

__global__ void __launch_bounds__(256)
scatter_kernel(const int* __restrict__ src, const int* __restrict__ dst) {
    int e = blockIdx.x * blockDim.x + threadIdx.x;
    if (e >= EE) return;
    int p = atomicAdd(&g_cnt[dst[e]], 1);
    g_csrc[p] = src[e];
}

// ====================== SGEMM: g_feat[M,N] = A[M,K] @ B[K,N] ======================
// BMx(TBN) tile, BK=16, 256 threads, 8x(TBN/16) per thread, double-buffered, FFMA2.
template<int TBN>
__device__ __forceinline__ void load_tile(
    const float* __restrict__ A, const float* __restrict__ B,
    int M, int N, int K, int row0, int col0, int k0, int tid,
    float (* __restrict__ As)[BM + 2], float (* __restrict__ Bs)[TBN]) {
    #pragma unroll
    for (int t = 0; t < 2; t++) {
        // A tile: 128 rows x 16 k, transposed into As[k][m]
        int fi = tid + t * 256;
        int row = fi >> 2, kq = fi & 3;
        int gr = row0 + row;
        float4 v = make_float4(0.f, 0.f, 0.f, 0.f);
        if (gr < M) v = *(const float4*)&A[(long)gr * K + k0 + kq * 4];
        As[kq * 4 + 0][row] = v.x;
        As[kq * 4 + 1][row] = v.y;
        As[kq * 4 + 2][row] = v.z;
        As[kq * 4 + 3][row] = v.w;
    }
    #pragma unroll
    for (int t = 0; t < TBN / 64; t++) {
        // B tile: 16 k x TBN cols
        int fi = tid + t * 256;
        int krow = fi / (TBN / 4), nq = fi % (TBN / 4);
        int gc = col0 + nq * 4;
        float4 v = make_float4(0.f, 0.f, 0.f, 0.f);
        if (gc < N) v = *(const float4*)&B[(long)(k0 + krow) * N + gc];
        *(float4*)&Bs[krow][nq * 4] = v;
    }
}

template<int TBN>
__global__ void __launch_bounds__(256)
sgemm_kernel(const float* __restrict__ A, const float* __restrict__ B,
             int M, int N, int K) {
    constexpr int CPT = TBN / 16;          // cols per thread (8 or 4)
    __shared__ __align__(16) float As[2][BK][BM + 2];
    __shared__ __align__(16) float Bs[2][BK][TBN];
    const int tid = threadIdx.x;
    const int tx = tid & 15;
    const int ty = tid >> 4;
    const int row0 = blockIdx.x * BM;
    const int col0 = blockIdx.y * TBN;

    unsigned long long acc[4][CPT];
    #pragma unroll
    for (int r = 0; r < 4; r++)
        #pragma unroll
        for (int j = 0; j < CPT; j++) acc[r][j] = 0ull;

    load_tile<TBN>(A, B, M, N, K, row0, col0, 0, tid, As[0], Bs[0]);
    __syncthreads();

    int buf = 0;
    for (int k0 = 0; k0 < K; k0 += BK) {
        if (k0 + BK < K)
            load_tile<TBN>(A, B, M, N, K, row0, col0, k0 + BK, tid, As[buf ^ 1], Bs[buf ^ 1]);
        #pragma unroll
        for (int kk = 0; kk < BK; kk++) {
            unsigned long long ap[4];
            #pragma unroll
            for (int r = 0; r < 4; r++)
                ap[r] = *(const unsigned long long*)&As[buf][kk][ty * 8 + r * 2];
            unsigned long long bd[CPT];
            #pragma unroll
            for (int j = 0; j < CPT; j++) {
                float bv = Bs[buf][kk][tx * CPT + j];
                asm("mov.b64 %0, {%1, %1};" : "=l"(bd[j]) : "f"(bv));
            }
            #pragma unroll
            for (int r = 0; r < 4; r++)
                #pragma unroll
                for (int j = 0; j < CPT; j++)
                    asm("fma.rn.f32x2 %0, %1, %2, %0;"
                        : "+l"(acc[r][j]) : "l"(ap[r]), "l"(bd[j]));
        }
        __syncthreads();
        buf ^= 1;
    }

    const int cbase = col0 + tx * CPT;
    #pragma unroll
    for (int r = 0; r < 4; r++) {
        float lo[CPT], hi[CPT];
        #pragma unroll
        for (int j = 0; j < CPT; j++)
            asm("mov.b64 {%0, %1}, %2;" : "=f"(lo[j]), "=f"(hi[j]) : "l"(acc[r][j]));
        int gr0 = row0 + ty * 8 + 2 * r;
        #pragma unroll
        for (int p = 0; p < 2; p++) {
            int gr = gr0 + p;
            if (gr >= M) continue;
            const float* c = p ? hi : lo;
            if (cbase + CPT - 1 < N) {
                #pragma unroll
                for (int q = 0; q < CPT / 4; q++)
                    *(float4*)&g_feat[(long)gr * N + cbase + q * 4] =
                        make_float4(c[q * 4], c[q * 4 + 1], c[q * 4 + 2], c[q * 4 + 3]);
            } else {
                for (int jj = 0; jj < CPT; jj++)
                    if (cbase + jj < N) g_feat[(long)gr * N + cbase + jj] = c[jj];
            }
        }
    }
}

// ====================== el/er per (node, head) ======================
__global__ void __launch_bounds__(256)
elr_kernel(const float* __restrict__ al, const float* __restrict__ ar, int od) {
    int idx = blockIdx.x * blockDim.x + threadIdx.x;   // n*H + h
    if (idx >= NN * HH) return;
    int n = idx >> 2, h = idx & 3;
    const float* f = g_feat + (long)n * HH * od + h * od;
    const float* alh = al + h * od;
    const float* arh = ar + h * od;
    float sl = 0.f, sr = 0.f;
    if (od == DD) {
        #pragma unroll
        for (int d = 0; d < DD; d += 4) {
            float4 v = *(const float4*)&f[d];
            float4 a = *(const float4*)&alh[d];
            float4 r = *(const float4*)&arh[d];
            sl += v.x * a.x + v.y * a.y + v.z * a.z + v.w * a.w;
            sr += v.x * r.x + v.y * r.y + v.z * r.z + v.w * r.w;
        }
    } else {
        for (int d = 0; d < od; d++) { float v = f[d]; sl += v * alh[d]; sr += v * arh[d]; }
    }
    g_el[idx] = sl;
    g_er[idx] = sr;
}

__device__ __forceinline__ float lrelu(float v) { return v > 0.f ? v : NEG_SLOPE * v; }

__device__ __forceinline__ float pick4(float4 v, int h) {
    float ab = (h & 1) ? v.y : v.x;
    float cd = (h & 1) ? v.w : v.z;
    return (h & 2) ? cd : ab;
}

// ====================== FUSED softmax+aggregation F=128 (warp per node) ======================
// out[node] = relu( (sum_e ex_e * feat[src_e]) / den + bias ),  ex = exp(e - m)
__global__ void __launch_bounds__(256)
agg128_fused(const float* __restrict__ bias) {
    __shared__ float4 sh_ex [8][32];
    __shared__ int    sh_src[8][32];
    int node = (blockIdx.x * blockDim.x + threadIdx.x) >> 5;
    int lane = threadIdx.x & 31;
    int wid = threadIdx.x >> 5;
    if (node >= NN) return;
    int r0 = g_rowptr[node], r1 = g_rowptr[node + 1];
    const int head = lane >> 3;

    float4 erd = *(const float4*)&g_er[node * 4];

    // pass 1: per-head max (edge-per-lane)
    float mx0 = -CUDART_INF_F, mx1 = -CUDART_INF_F, mx2 = -CUDART_INF_F, mx3 = -CUDART_INF_F;
    for (int i = r0 + lane; i < r1; i += 32) {
        int s = g_csrc[i];
        float4 ev = *(const float4*)&g_el[s * 4];
        mx0 = fmaxf(mx0, lrelu(ev.x + erd.x));
        mx1 = fmaxf(mx1, lrelu(ev.y + erd.y));
        mx2 = fmaxf(mx2, lrelu(ev.z + erd.z));
        mx3 = fmaxf(mx3, lrelu(ev.w + erd.w));
    }
    #pragma unroll
    for (int o = 16; o > 0; o >>= 1) {
        mx0 = fmaxf(mx0, __shfl_xor_sync(0xffffffffu, mx0, o));
        mx1 = fmaxf(mx1, __shfl_xor_sync(0xffffffffu, mx1, o));
        mx2 = fmaxf(mx2, __shfl_xor_sync(0xffffffffu, mx2, o));
        mx3 = fmaxf(mx3, __shfl_xor_sync(0xffffffffu, mx3, o));
    }

    // pass 2: chunks of 32 edges: ex -> smem (edge-per-lane), then aggregate (feat-per-lane)
    float den0 = 0.f, den1 = 0.f, den2 = 0.f, den3 = 0.f;
    float4 acc = {0.f, 0.f, 0.f, 0.f};
    for (int c0 = r0; c0 < r1; c0 += 32) {
        int n = min(32, r1 - c0);
        if (lane < n) {
            int s = g_csrc[c0 + lane];
            float4 ev = *(const float4*)&g_el[s * 4];
            float4 ex;
            ex.x = __expf(lrelu(ev.x + erd.x) - mx0);
            ex.y = __expf(lrelu(ev.y + erd.y) - mx1);
            ex.z = __expf(lrelu(ev.z + erd.z) - mx2);
            ex.w = __expf(lrelu(ev.w + erd.w) - mx3);
            sh_ex[wid][lane] = ex;
            sh_src[wid][lane] = s;
            den0 += ex.x; den1 += ex.y; den2 += ex.z; den3 += ex.w;
        }
        __syncwarp();
        int k = 0;
        #pragma unroll 1
        for (; k + 3 < n; k += 4) {
            float a0 = pick4(sh_ex[wid][k],     head);
            float a1 = pick4(sh_ex[wid][k + 1], head);
            float a2 = pick4(sh_ex[wid][k + 2], head);
            float a3 = pick4(sh_ex[wid][k + 3], head);
            int s0 = sh_src[wid][k],     s1 = sh_src[wid][k + 1];
            int s2 = sh_src[wid][k + 2], s3 = sh_src[wid][k + 3];
            float4 f0 = *(const float4*)&g_feat[(long)s0 * 128 + lane * 4];
            float4 f1 = *(const float4*)&g_feat[(long)s1 * 128 + lane * 4];
            float4 f2 = *(const float4*)&g_feat[(long)s2 * 128 + lane * 4];
            float4 f3 = *(const float4*)&g_feat[(long)s3 * 128 + lane * 4];
            acc.x += a0 * f0.x + a1 * f1.x + a2 * f2.x + a3 * f3.x;
            acc.y += a0 * f0.y + a1 * f1.y + a2 * f2.y + a3 * f3.y;
            acc.z += a0 * f0.z + a1 * f1.z + a2 * f2.z + a3 * f3.z;
            acc.w += a0 * f0.w + a1 * f1.w + a2 * f2.w + a3 * f3.w;
        }
        for (; k < n; k++) {
            float a = pick4(sh_ex[wid][k], head);
            int s = sh_src[wid][k];
            float4 f = *(const float4*)&g_feat[(long)s * 128 + lane * 4];
            acc.x += a * f.x; acc.y += a * f.y; acc.z += a * f.z; acc.w += a * f.w;
        }
        __syncwarp();
    }
    // reduce den, normalize, bias, relu, store
    #pragma unroll
    for (int o = 16; o > 0; o >>= 1) {
        den0 += __shfl_xor_sync(0xffffffffu, den0, o);
        den1 += __shfl_xor_sync(0xffffffffu, den1, o);
        den2 += __shfl_xor_sync(0xffffffffu, den2, o);
        den3 += __shfl_xor_sync(0xffffffffu, den3, o);
    }
    float4 dv = make_float4(den0, den1, den2, den3);
    float dh = pick4(dv, head);
    float invh = (dh > 0.f) ? 1.f / dh : 0.f;
    float4 b = *(const float4*)&bias[lane * 4];
    acc.x = fmaxf(acc.x * invh + b.x, 0.f);
    acc.y = fmaxf(acc.y * invh + b.y, 0.f);
    acc.z = fmaxf(acc.z * invh + b.z, 0.f);
    acc.w = fmaxf(acc.w * invh + b.w, 0.f);
    *(float4*)&g_out[(long)node * 128 + lane * 4] = acc;
}

// ====================== FUSED softmax+aggregation F=188 (warp per node; no bias/act) ======================
__global__ void __launch_bounds__(256)
agg188_fused() {
    __shared__ float4 sh_ex [8][32];
    __shared__ int    sh_src[8][32];
    int node = (blockIdx.x * blockDim.x + threadIdx.x) >> 5;
    int lane = threadIdx.x & 31;
    int wid = threadIdx.x >> 5;
    if (node >= NN) return;
    int r0 = g_rowptr[node], r1 = g_rowptr[node + 1];

    float4 erd = *(const float4*)&g_er[node * 4];

    // pass 1: per-head max
    float mx0 = -CUDART_INF_F, mx1 = -CUDART_INF_F, mx2 = -CUDART_INF_F, mx3 = -CUDART_INF_F;
    for (int i = r0 + lane; i < r1; i += 32) {
        int s = g_csrc[i];
        float4 ev = *(const float4*)&g_el[s * 4];
        mx0 = fmaxf(mx0, lrelu(ev.x + erd.x));
        mx1 = fmaxf(mx1, lrelu(ev.y + erd.y));
        mx2 = fmaxf(mx2, lrelu(ev.z + erd.z));
        mx3 = fmaxf(mx3, lrelu(ev.w + erd.w));
    }
    #pragma unroll
    for (int o = 16; o > 0; o >>= 1) {
        mx0 = fmaxf(mx0, __shfl_xor_sync(0xffffffffu, mx0, o));
        mx1 = fmaxf(mx1, __shfl_xor_sync(0xffffffffu, mx1, o));
        mx2 = fmaxf(mx2, __shfl_xor_sync(0xffffffffu, mx2, o));
        mx3 = fmaxf(mx3, __shfl_xor_sync(0xffffffffu, mx3, o));
    }

    float den0 = 0.f, den1 = 0.f, den2 = 0.f, den3 = 0.f;
    float acc[6] = {0.f, 0.f, 0.f, 0.f, 0.f, 0.f};
    int headk[6];
    #pragma unroll
    for (int k = 0; k < 6; k++) headk[k] = (lane + 32 * k) / CC;  // feature/47

    for (int c0 = r0; c0 < r1; c0 += 32) {
        int n = min(32, r1 - c0);
        if (lane < n) {
            int s = g_csrc[c0 + lane];
            float4 ev = *(const float4*)&g_el[s * 4];
            float4 ex;
            ex.x = __expf(lrelu(ev.x + erd.x) - mx0);
            ex.y = __expf(lrelu(ev.y + erd.y) - mx1);
            ex.z = __expf(lrelu(ev.z + erd.z) - mx2);
            ex.w = __expf(lrelu(ev.w + erd.w) - mx3);
            sh_ex[wid][lane] = ex;
            sh_src[wid][lane] = s;
            den0 += ex.x; den1 += ex.y; den2 += ex.z; den3 += ex.w;
        }
        __syncwarp();
        #pragma unroll 1
        for (int k = 0; k < n; k++) {
            float4 ex4 = sh_ex[wid][k];
            int s = sh_src[wid][k];
            const float* fs = g_feat + (long)s * 188;
            #pragma unroll
            for (int q = 0; q < 6; q++) {
                int j = lane + 32 * q;
                if (j < 188) acc[q] += pick4(ex4, headk[q]) * fs[j];
            }
        }
        __syncwarp();
    }
    #pragma unroll
    for (int o = 16; o > 0; o >>= 1) {
        den0 += __shfl_xor_sync(0xffffffffu, den0, o);
        den1 += __shfl_xor_sync(0xffffffffu, den1, o);
        den2 += __shfl_xor_sync(0xffffffffu, den2, o);
        den3 += __shfl_xor_sync(0xffffffffu, den3, o);
    }
    float4 dv = make_float4(den0, den1, den2, den3);
    float* op = g_out + (long)node * 188;
    #pragma unroll
    for (int q = 0; q < 6; q++) {
        int j = lane + 32 * q;
        if (j < 188) {
            float dh = pick4(dv, headk[q]);
            float invh = (dh > 0.f) ? 1.f / dh : 0.f;
            op[j] = acc[q] * invh;
        }
    }
}

// ====================== final: head-mean (+bias) + log_softmax (warp per node) ======================
__global__ void __launch_bounds__(256)
final_kernel(const float* __restrict__ b3, float* __restrict__ y) {
    int node = (blockIdx.x * blockDim.x + threadIdx.x) >> 5;
    int lane = threadIdx.x & 31;
    if (node >= NN) return;
    const float* row = g_out + (long)node * HH * CC;

    float a0 = 0.f, a1 = 0.f;
    float v0 = -CUDART_INF_F, v1 = -CUDART_INF_F;
    if (lane < CC) {
        float sum = 0.f;
        #pragma unroll
        for (int h = 0; h < HH; h++) sum += row[h * CC + lane] + b3[h * CC + lane];
        a0 = sum * 0.25f; v0 = a0;
    }
    int c1 = lane + 32;
    if (c1 < CC) {
        float sum = 0.f;
        #pragma unroll
        for (int h = 0; h < HH; h++) sum += row[h * CC + c1] + b3[h * CC + c1];
        a1 = sum * 0.25f; v1 = a1;
    }
    float mx = fmaxf(v0, v1);
    #pragma unroll
    for (int o = 16; o > 0; o >>= 1) mx = fmaxf(mx, __shfl_xor_sync(0xffffffffu, mx, o));
    float s = 0.f;
    if (lane < CC) s += __expf(a0 - mx);
    if (c1 < CC)   s += __expf(a1 - mx);
    #pragma unroll
    for (int o = 16; o > 0; o >>= 1) s += __shfl_xor_sync(0xffffffffu, s, o);
    float lse = logf(s);
    if (lane < CC) y[(long)node * CC + lane] = a0 - mx - lse;
    if (c1 < CC)   y[(long)node * CC + c1] = a1 - mx - lse;
}

// ====================== host driver ======================
extern "C" void kernel_launch(void* const* d_in, const int* in_sizes, int n_in,
                              void* d_out, int out_size) {
    const float* x   = (const float*)d_in[0];
    const int*   src = (const int*)  d_in[1];
    const int*   dst = (const int*)  d_in[2];
    const float* W1  = (const float*)d_in[3];
    const float* al1 = (const float*)d_in[4];
    const float* ar1 = (const float*)d_in[5];
    const float* b1  = (const float*)d_in[6];
    const float* W2  = (const float*)d_in[7];
    const float* al2 = (const float*)d_in[8];
    const float* ar2 = (const float*)d_in[9];
    const float* b2  = (const float*)d_in[10];
    const float* W3  = (const float*)d_in[11];
    const float* al3 = (const float*)d_in[12];
    const float* ar3 = (const float*)d_in[13];
    const float* b3  = (const float*)d_in[14];
    float* y = (float*)d_out;

    static float* outb = nullptr;
    if (!outb) cudaGetSymbolAddress((void**)&outb, g_out);

    const int TB = 256;
    const int nodeWarpGrid = (NN + 7) / 8;

    // ---- CSR build (graph static across layers) ----
    zero_deg_kernel<<<(NN + TB - 1) / TB, TB>>>();
    hist_kernel<<<(EE + TB - 1) / TB, TB>>>(dst);
    scan_kernel<<<1, 1024>>>();
    scatter_kernel<<<(EE + TB - 1) / TB, TB>>>(src, dst);

    // ---- layer 1: x [N,256] -> g_out [N,128] ----
    {
        dim3 gg((NN + BM - 1) / BM, 1);
        sgemm_kernel<128><<<gg, TB>>>(x, W1, NN, 128, F_IN);
        elr_kernel<<<(NN * HH + TB - 1) / TB, TB>>>(al1, ar1, DD);
        agg128_fused<<<nodeWarpGrid, TB>>>(b1);
    }
    // ---- layer 2: g_out [N,128] -> g_out [N,128] ----
    {
        dim3 gg((NN + BM - 1) / BM, 1);
        sgemm_kernel<128><<<gg, TB>>>(outb, W2, NN, 128, 128);
        elr_kernel<<<(NN * HH + TB - 1) / TB, TB>>>(al2, ar2, DD);
        agg128_fused<<<nodeWarpGrid, TB>>>(b2);
    }
    // ---- layer 3: g_out [N,128] -> g_out [N,188] (BN=64 tiles; bias fused into final) ----
    {
        dim3 gg((NN + BM - 1) / BM, (188 + 63) / 64);
        sgemm_kernel<64><<<gg, TB>>>(outb, W3, NN, 188, 128);
        elr_kernel<<<(NN * HH + TB - 1) / TB, TB>>>(al3, ar3, CC);
        agg188_fused<<<nodeWarpGrid, TB>>>();
    }
    // ---- head-mean + bias + log_softmax ----
    final_kernel<<<(NN + 7) / 8, TB>>>(b3, y);
}

// round 10
// speedup vs baseline: 1.2525x; 1.1047x over previous
#include <cuda_runtime.h>
#include <cuda_bf16.h>
#include <math_constants.h>

#define NN 100000
#define EE 1600000
#define F_IN 256
#define HH 4
#define DD 32
#define CC 47
#define NEG_SLOPE 0.2f

#define BM 128
#define BK 16
#define NBLK ((NN + 255) / 256)   // 391

// ---------------- scratch (__device__ globals; no allocation) ----------------
__device__ float g_feat [NN * HH * CC];   // gemm output [N, H*od] (max 188 wide)
__device__ float g_out  [NN * HH * CC];   // aggregated output / next-layer input
__device__ float g_el   [NN * HH];        // [N,4] -> float4 per node
__device__ float g_er   [NN * HH];
__device__ int   g_deg  [NN];
__device__ int   g_cnt  [NN];             // scatter cursor (init = rowptr)
__device__ int   g_rowptr[NN + 1];
__device__ int   g_csrc [EE];             // src node per CSR position
__device__ int   g_bsum [512];            // block sums for 3-phase scan

// ====================== CSR build (once per launch) ======================
__global__ void __launch_bounds__(256)
zero_deg_kernel() {
    int i = blockIdx.x * blockDim.x + threadIdx.x;
    if (i < NN) g_deg[i] = 0;
}

__global__ void __launch_bounds__(256)
hist_kernel(const int* __restrict__ dst) {
    int e = blockIdx.x * blockDim.x + threadIdx.x;
    if (e < EE) atomicAdd(&g_deg[dst[e]], 1);
}

// phase 1: block-local exclusive scan of deg; write block totals
__global__ void __launch_bounds__(256)
scan1_kernel() {
    __shared__ int sh[256];
    int t = threadIdx.x, b = blockIdx.x;
    int i = b * 256 + t;
    int d = (i < NN) ? g_deg[i] : 0;
    sh[t] = d;
    __syncthreads();
    for (int o = 1; o < 256; o <<= 1) {
        int v = (t >= o) ? sh[t - o] : 0;
        __syncthreads();
        sh[t] += v;
        __syncthreads();
    }
    if (i < NN) g_rowptr[i] = sh[t] - d;       // local exclusive
    if (t == 255) g_bsum[b] = sh[255];
}

// phase 2: single small block scans the 391 block totals (exclusive)
__global__ void __launch_bounds__(512)
scan2_kernel() {
    __shared__ int sh[512];
    int t = threadIdx.x;
    int v = (t < NBLK) ? g_bsum[t] : 0;
    sh[t] = v;
    __syncthreads();
    for (int o = 1; o < 512; o <<= 1) {
        int u = (t >= o) ? sh[t - o] : 0;
        __syncthreads();
        sh[t] += u;
        __syncthreads();
    }
    g_bsum[t] = sh[t] - v;                     // exclusive
}

// phase 3: add block offsets; init cnt; rowptr[NN] = EE
__global__ void __launch_bounds__(256)
scan3_kernel() {
    int t = threadIdx.x, b = blockIdx.x;
    int i = b * 256 + t;
    if (i < NN) {
        int r = g_rowptr[i] + g_bsum[b];
        g_rowptr[i] = r;
        g_cnt[i] = r;
    }
    if (b == 0 && t == 0) g_rowptr[NN] = EE;
}

__global__ void __launch_bounds__(256)
scatter_kernel(const int* __restrict__ src, const int* __restrict__ dst) {
    int e = blockIdx.x * blockDim.x + threadIdx.x;
    if (e >= EE) return;
    int p = atomicAdd(&g_cnt[dst[e]], 1);
    g_csrc[p] = src[e];
}

// ====================== SGEMM: g_feat[M,N] = A[M,K] @ B[K,N] ======================
// BMx(TBN) tile, BK=16, 256 threads, 8x(TBN/16) per thread, double-buffered, FFMA2.
// B is stored DUPLICATED in smem: logical col n lives at (n%CPT)*32 + (n/CPT)*2 (+1 dup),
// so the f32x2 multiplier pair is a direct conflict-free LDS.64 (no mov.b64 {b,b}).
// Stride 32 per j-group: 16 tx-slots x 2 floats = 32 floats, no overlap.
template<int TBN>
__device__ __forceinline__ void load_tile(
    const float* __restrict__ A, const float* __restrict__ B,
    int M, int N, int K, int row0, int col0, int k0, int tid,
    float (* __restrict__ As)[BM + 2], float* __restrict__ Bs /* [BK][BROW] */) {
    constexpr int CPT = TBN / 16;
    constexpr int BROW = CPT * 32;
    #pragma unroll
    for (int t = 0; t < 2; t++) {
        // A tile: 128 rows x 16 k, transposed into As[k][m]
        int fi = tid + t * 256;
        int row = fi >> 2, kq = fi & 3;
        int gr = row0 + row;
        float4 v = make_float4(0.f, 0.f, 0.f, 0.f);
        if (gr < M) v = *(const float4*)&A[(long)gr * K + k0 + kq * 4];
        As[kq * 4 + 0][row] = v.x;
        As[kq * 4 + 1][row] = v.y;
        As[kq * 4 + 2][row] = v.z;
        As[kq * 4 + 3][row] = v.w;
    }
    #pragma unroll
    for (int t = 0; t < TBN / 64; t++) {
        // B tile: 16 k x TBN cols, duplicated layout
        int fi = tid + t * 256;
        int krow = fi / (TBN / 4), nq = fi % (TBN / 4);
        int gc = col0 + nq * 4;
        float4 v = make_float4(0.f, 0.f, 0.f, 0.f);
        if (gc < N) v = *(const float4*)&B[(long)(k0 + krow) * N + gc];
        float vv[4] = {v.x, v.y, v.z, v.w};
        #pragma unroll
        for (int e = 0; e < 4; e++) {
            int n = nq * 4 + e;
            int addr = (n % CPT) * 32 + (n / CPT) * 2;
            *(float2*)&Bs[krow * BROW + addr] = make_float2(vv[e], vv[e]);
        }
    }
}

template<int TBN>
__global__ void __launch_bounds__(256)
sgemm_kernel(const float* __restrict__ A, const float* __restrict__ B,
             int M, int N, int K) {
    constexpr int CPT = TBN / 16;          // cols per thread (8 or 4)
    constexpr int BROW = CPT * 32;
    __shared__ __align__(16) float As[2][BK][BM + 2];
    __shared__ __align__(16) float Bs[2][BK * BROW];
    const int tid = threadIdx.x;
    const int tx = tid & 15;
    const int ty = tid >> 4;
    const int row0 = blockIdx.x * BM;
    const int col0 = blockIdx.y * TBN;

    unsigned long long acc[4][CPT];
    #pragma unroll
    for (int r = 0; r < 4; r++)
        #pragma unroll
        for (int j = 0; j < CPT; j++) acc[r][j] = 0ull;

    load_tile<TBN>(A, B, M, N, K, row0, col0, 0, tid, As[0], Bs[0]);
    __syncthreads();

    int buf = 0;
    for (int k0 = 0; k0 < K; k0 += BK) {
        if (k0 + BK < K)
            load_tile<TBN>(A, B, M, N, K, row0, col0, k0 + BK, tid, As[buf ^ 1], Bs[buf ^ 1]);
        #pragma unroll
        for (int kk = 0; kk < BK; kk++) {
            unsigned long long ap[4];
            #pragma unroll
            for (int r = 0; r < 4; r++)
                ap[r] = *(const unsigned long long*)&As[buf][kk][ty * 8 + r * 2];
            unsigned long long bd[CPT];
            #pragma unroll
            for (int j = 0; j < CPT; j++)
                bd[j] = *(const unsigned long long*)&Bs[buf][kk * BROW + j * 32 + tx * 2];
            #pragma unroll
            for (int r = 0; r < 4; r++)
                #pragma unroll
                for (int j = 0; j < CPT; j++)
                    asm("fma.rn.f32x2 %0, %1, %2, %0;"
                        : "+l"(acc[r][j]) : "l"(ap[r]), "l"(bd[j]));
        }
        __syncthreads();
        buf ^= 1;
    }

    const int cbase = col0 + tx * CPT;
    #pragma unroll
    for (int r = 0; r < 4; r++) {
        float lo[CPT], hi[CPT];
        #pragma unroll
        for (int j = 0; j < CPT; j++)
            asm("mov.b64 {%0, %1}, %2;" : "=f"(lo[j]), "=f"(hi[j]) : "l"(acc[r][j]));
        int gr0 = row0 + ty * 8 + 2 * r;
        #pragma unroll
        for (int p = 0; p < 2; p++) {
            int gr = gr0 + p;
            if (gr >= M) continue;
            const float* c = p ? hi : lo;
            if (cbase + CPT - 1 < N) {
                #pragma unroll
                for (int q = 0; q < CPT / 4; q++)
                    *(float4*)&g_feat[(long)gr * N + cbase + q * 4] =
                        make_float4(c[q * 4], c[q * 4 + 1], c[q * 4 + 2], c[q * 4 + 3]);
            } else {
                for (int jj = 0; jj < CPT; jj++)
                    if (cbase + jj < N) g_feat[(long)gr * N + cbase + jj] = c[jj];
            }
        }
    }
}

// ====================== el/er per (node, head) ======================
__global__ void __launch_bounds__(256)
elr_kernel(const float* __restrict__ al, const float* __restrict__ ar, int od) {
    int idx = blockIdx.x * blockDim.x + threadIdx.x;   // n*H + h
    if (idx >= NN * HH) return;
    int n = idx >> 2, h = idx & 3;
    const float* f = g_feat + (long)n * HH * od + h * od;
    const float* alh = al + h * od;
    const float* arh = ar + h * od;
    float sl = 0.f, sr = 0.f;
    if (od == DD) {
        #pragma unroll
        for (int d = 0; d < DD; d += 4) {
            float4 v = *(const float4*)&f[d];
            float4 a = *(const float4*)&alh[d];
            float4 r = *(const float4*)&arh[d];
            sl += v.x * a.x + v.y * a.y + v.z * a.z + v.w * a.w;
            sr += v.x * r.x + v.y * r.y + v.z * r.z + v.w * r.w;
        }
    } else {
        for (int d = 0; d < od; d++) { float v = f[d]; sl += v * alh[d]; sr += v * arh[d]; }
    }
    g_el[idx] = sl;
    g_er[idx] = sr;
}

__device__ __forceinline__ float lrelu(float v) { return v > 0.f ? v : NEG_SLOPE * v; }

__device__ __forceinline__ float pick4(float4 v, int h) {
    float ab = (h & 1) ? v.y : v.x;
    float cd = (h & 1) ? v.w : v.z;
    return (h & 2) ? cd : ab;
}

// ====================== FUSED softmax+aggregation F=128 (warp per node) ======================
// No max-subtraction: ex = exp(lrelu(el+er)) directly (|e| << 88 by construction).
// out[node] = relu( (sum_e ex_e * feat[src_e]) / den + bias )
__global__ void __launch_bounds__(256)
agg128_fused(const float* __restrict__ bias) {
    __shared__ float4 sh_ex [8][32];
    __shared__ int    sh_src[8][32];
    int node = (blockIdx.x * blockDim.x + threadIdx.x) >> 5;
    int lane = threadIdx.x & 31;
    int wid = threadIdx.x >> 5;
    if (node >= NN) return;
    int r0 = g_rowptr[node], r1 = g_rowptr[node + 1];
    const int head = lane >> 3;

    float4 erd = *(const float4*)&g_er[node * 4];

    float den0 = 0.f, den1 = 0.f, den2 = 0.f, den3 = 0.f;
    float4 acc = {0.f, 0.f, 0.f, 0.f};
    for (int c0 = r0; c0 < r1; c0 += 32) {
        int n = min(32, r1 - c0);
        if (lane < n) {
            int s = g_csrc[c0 + lane];
            float4 ev = *(const float4*)&g_el[s * 4];
            float4 ex;
            ex.x = __expf(lrelu(ev.x + erd.x));
            ex.y = __expf(lrelu(ev.y + erd.y));
            ex.z = __expf(lrelu(ev.z + erd.z));
            ex.w = __expf(lrelu(ev.w + erd.w));
            sh_ex[wid][lane] = ex;
            sh_src[wid][lane] = s;
            den0 += ex.x; den1 += ex.y; den2 += ex.z; den3 += ex.w;
        }
        __syncwarp();
        int k = 0;
        #pragma unroll 1
        for (; k + 3 < n; k += 4) {
            float a0 = pick4(sh_ex[wid][k],     head);
            float a1 = pick4(sh_ex[wid][k + 1], head);
            float a2 = pick4(sh_ex[wid][k + 2], head);
            float a3 = pick4(sh_ex[wid][k + 3], head);
            int s0 = sh_src[wid][k],     s1 = sh_src[wid][k + 1];
            int s2 = sh_src[wid][k + 2], s3 = sh_src[wid][k + 3];
            float4 f0 = *(const float4*)&g_feat[(long)s0 * 128 + lane * 4];
            float4 f1 = *(const float4*)&g_feat[(long)s1 * 128 + lane * 4];
            float4 f2 = *(const float4*)&g_feat[(long)s2 * 128 + lane * 4];
            float4 f3 = *(const float4*)&g_feat[(long)s3 * 128 + lane * 4];
            acc.x += a0 * f0.x + a1 * f1.x + a2 * f2.x + a3 * f3.x;
            acc.y += a0 * f0.y + a1 * f1.y + a2 * f2.y + a3 * f3.y;
            acc.z += a0 * f0.z + a1 * f1.z + a2 * f2.z + a3 * f3.z;
            acc.w += a0 * f0.w + a1 * f1.w + a2 * f2.w + a3 * f3.w;
        }
        for (; k < n; k++) {
            float a = pick4(sh_ex[wid][k], head);
            int s = sh_src[wid][k];
            float4 f = *(const float4*)&g_feat[(long)s * 128 + lane * 4];
            acc.x += a * f.x; acc.y += a * f.y; acc.z += a * f.z; acc.w += a * f.w;
        }
        __syncwarp();
    }
    #pragma unroll
    for (int o = 16; o > 0; o >>= 1) {
        den0 += __shfl_xor_sync(0xffffffffu, den0, o);
        den1 += __shfl_xor_sync(0xffffffffu, den1, o);
        den2 += __shfl_xor_sync(0xffffffffu, den2, o);
        den3 += __shfl_xor_sync(0xffffffffu, den3, o);
    }
    float4 dv = make_float4(den0, den1, den2, den3);
    float dh = pick4(dv, head);
    float invh = (dh > 0.f) ? 1.f / dh : 0.f;
    float4 b = *(const float4*)&bias[lane * 4];
    acc.x = fmaxf(acc.x * invh + b.x, 0.f);
    acc.y = fmaxf(acc.y * invh + b.y, 0.f);
    acc.z = fmaxf(acc.z * invh + b.z, 0.f);
    acc.w = fmaxf(acc.w * invh + b.w, 0.f);
    *(float4*)&g_out[(long)node * 128 + lane * 4] = acc;
}

// ====================== FUSED softmax+aggregation F=188 (warp per node; no bias/act) ======================
__global__ void __launch_bounds__(256)
agg188_fused() {
    __shared__ float4 sh_ex [8][32];
    __shared__ int    sh_src[8][32];
    int node = (blockIdx.x * blockDim.x + threadIdx.x) >> 5;
    int lane = threadIdx.x & 31;
    int wid = threadIdx.x >> 5;
    if (node >= NN) return;
    int r0 = g_rowptr[node], r1 = g_rowptr[node + 1];

    float4 erd = *(const float4*)&g_er[node * 4];

    float den0 = 0.f, den1 = 0.f, den2 = 0.f, den3 = 0.f;
    float acc[6] = {0.f, 0.f, 0.f, 0.f, 0.f, 0.f};
    int headk[6];
    #pragma unroll
    for (int k = 0; k < 6; k++) headk[k] = (lane + 32 * k) / CC;  // feature/47

    for (int c0 = r0; c0 < r1; c0 += 32) {
        int n = min(32, r1 - c0);
        if (lane < n) {
            int s = g_csrc[c0 + lane];
            float4 ev = *(const float4*)&g_el[s * 4];
            float4 ex;
            ex.x = __expf(lrelu(ev.x + erd.x));
            ex.y = __expf(lrelu(ev.y + erd.y));
            ex.z = __expf(lrelu(ev.z + erd.z));
            ex.w = __expf(lrelu(ev.w + erd.w));
            sh_ex[wid][lane] = ex;
            sh_src[wid][lane] = s;
            den0 += ex.x; den1 += ex.y; den2 += ex.z; den3 += ex.w;
        }
        __syncwarp();
        #pragma unroll 1
        for (int k = 0; k < n; k++) {
            float4 ex4 = sh_ex[wid][k];
            int s = sh_src[wid][k];
            const float* fs = g_feat + (long)s * 188;
            #pragma unroll
            for (int q = 0; q < 6; q++) {
                int j = lane + 32 * q;
                if (j < 188) acc[q] += pick4(ex4, headk[q]) * fs[j];
            }
        }
        __syncwarp();
    }
    #pragma unroll
    for (int o = 16; o > 0; o >>= 1) {
        den0 += __shfl_xor_sync(0xffffffffu, den0, o);
        den1 += __shfl_xor_sync(0xffffffffu, den1, o);
        den2 += __shfl_xor_sync(0xffffffffu, den2, o);
        den3 += __shfl_xor_sync(0xffffffffu, den3, o);
    }
    float4 dv = make_float4(den0, den1, den2, den3);
    float* op = g_out + (long)node * 188;
    #pragma unroll
    for (int q = 0; q < 6; q++) {
        int j = lane + 32 * q;
        if (j < 188) {
            float dh = pick4(dv, headk[q]);
            float invh = (dh > 0.f) ? 1.f / dh : 0.f;
            op[j] = acc[q] * invh;
        }
    }
}

// ====================== final: head-mean (+bias) + log_softmax (warp per node) ======================
__global__ void __launch_bounds__(256)
final_kernel(const float* __restrict__ b3, float* __restrict__ y) {
    int node = (blockIdx.x * blockDim.x + threadIdx.x) >> 5;
    int lane = threadIdx.x & 31;
    if (node >= NN) return;
    const float* row = g_out + (long)node * HH * CC;

    float a0 = 0.f, a1 = 0.f;
    float v0 = -CUDART_INF_F, v1 = -CUDART_INF_F;
    if (lane < CC) {
        float sum = 0.f;
        #pragma unroll
        for (int h = 0; h < HH; h++) sum += row[h * CC + lane] + b3[h * CC + lane];
        a0 = sum * 0.25f; v0 = a0;
    }
    int c1 = lane + 32;
    if (c1 < CC) {
        float sum = 0.f;
        #pragma unroll
        for (int h = 0; h < HH; h++) sum += row[h * CC + c1] + b3[h * CC + c1];
        a1 = sum * 0.25f; v1 = a1;
    }
    float mx = fmaxf(v0, v1);
    #pragma unroll
    for (int o = 16; o > 0; o >>= 1) mx = fmaxf(mx, __shfl_xor_sync(0xffffffffu, mx, o));
    float s = 0.f;
    if (lane < CC) s += __expf(a0 - mx);
    if (c1 < CC)   s += __expf(a1 - mx);
    #pragma unroll
    for (int o = 16; o > 0; o >>= 1) s += __shfl_xor_sync(0xffffffffu, s, o);
    float lse = logf(s);
    if (lane < CC) y[(long)node * CC + lane] = a0 - mx - lse;
    if (c1 < CC)   y[(long)node * CC + c1] = a1 - mx - lse;
}

// ====================== host driver ======================
extern "C" void kernel_launch(void* const* d_in, const int* in_sizes, int n_in,
                              void* d_out, int out_size) {
    const float* x   = (const float*)d_in[0];
    const int*   src = (const int*)  d_in[1];
    const int*   dst = (const int*)  d_in[2];
    const float* W1  = (const float*)d_in[3];
    const float* al1 = (const float*)d_in[4];
    const float* ar1 = (const float*)d_in[5];
    const float* b1  = (const float*)d_in[6];
    const float* W2  = (const float*)d_in[7];
    const float* al2 = (const float*)d_in[8];
    const float* ar2 = (const float*)d_in[9];
    const float* b2  = (const float*)d_in[10];
    const float* W3  = (const float*)d_in[11];
    const float* al3 = (const float*)d_in[12];
    const float* ar3 = (const float*)d_in[13];
    const float* b3  = (const float*)d_in[14];
    float* y = (float*)d_out;

    static float* outb = nullptr;
    if (!outb) cudaGetSymbolAddress((void**)&outb, g_out);

    const int TB = 256;
    const int nodeWarpGrid = (NN + 7) / 8;

    // ---- CSR build (graph static across layers) ----
    zero_deg_kernel<<<(NN + TB - 1) / TB, TB>>>();
    hist_kernel<<<(EE + TB - 1) / TB, TB>>>(dst);
    scan1_kernel<<<NBLK, TB>>>();
    scan2_kernel<<<1, 512>>>();
    scan3_kernel<<<NBLK, TB>>>();
    scatter_kernel<<<(EE + TB - 1) / TB, TB>>>(src, dst);

    // ---- layer 1: x [N,256] -> g_out [N,128] ----
    {
        dim3 gg((NN + BM - 1) / BM, 1);
        sgemm_kernel<128><<<gg, TB>>>(x, W1, NN, 128, F_IN);
        elr_kernel<<<(NN * HH + TB - 1) / TB, TB>>>(al1, ar1, DD);
        agg128_fused<<<nodeWarpGrid, TB>>>(b1);
    }
    // ---- layer 2: g_out [N,128] -> g_out [N,128] ----
    {
        dim3 gg((NN + BM - 1) / BM, 1);
        sgemm_kernel<128><<<gg, TB>>>(outb, W2, NN, 128, 128);
        elr_kernel<<<(NN * HH + TB - 1) / TB, TB>>>(al2, ar2, DD);
        agg128_fused<<<nodeWarpGrid, TB>>>(b2);
    }
    // ---- layer 3: g_out [N,128] -> g_out [N,188] (BN=64 tiles; bias fused into final) ----
    {
        dim3 gg((NN + BM - 1) / BM, (188 + 63) / 64);
        sgemm_kernel<64><<<gg, TB>>>(outb, W3, NN, 188, 128);
        elr_kernel<<<(NN * HH + TB - 1) / TB, TB>>>(al3, ar3, CC);
        agg188_fused<<<nodeWarpGrid, TB>>>();
    }
    // ---- head-mean + bias + log_softmax ----
    final_kernel<<<(NN + 7) / 8, TB>>>(b3, y);
}

// round 11
// speedup vs baseline: 1.3646x; 1.0895x over previous
#include <cuda_runtime.h>
#include <cuda_bf16.h>
#include <math_constants.h>

#define NN 100000
#define EE 1600000
#define F_IN 256
#define HH 4
#define DD 32
#define CC 47
#define NEG_SLOPE 0.2f

#define BM 128
#define BK 16
#define NBLK ((NN + 255) / 256)   // 391

// ---------------- scratch (__device__ globals; no allocation) ----------------
__device__ float g_feat [NN * HH * CC];
__device__ float g_out  [NN * HH * CC];
__device__ float g_el   [NN * HH];
__device__ float g_er   [NN * HH];
__device__ int   g_deg  [NN];
__device__ int   g_cnt  [NN];
__device__ int   g_rowptr[NN + 1];
__device__ int   g_csrc [EE];
__device__ int   g_bsum [512];

// ====================== CSR build (once per launch, side stream) ======================
__global__ void __launch_bounds__(256)
zero_deg_kernel() {
    int i = blockIdx.x * blockDim.x + threadIdx.x;
    if (i < NN) g_deg[i] = 0;
}

__global__ void __launch_bounds__(256)
hist_kernel(const int* __restrict__ dst) {
    int e = blockIdx.x * blockDim.x + threadIdx.x;
    if (e < EE) atomicAdd(&g_deg[dst[e]], 1);
}

__global__ void __launch_bounds__(256)
scan1_kernel() {
    __shared__ int sh[256];
    int t = threadIdx.x, b = blockIdx.x;
    int i = b * 256 + t;
    int d = (i < NN) ? g_deg[i] : 0;
    sh[t] = d;
    __syncthreads();
    for (int o = 1; o < 256; o <<= 1) {
        int v = (t >= o) ? sh[t - o] : 0;
        __syncthreads();
        sh[t] += v;
        __syncthreads();
    }
    if (i < NN) g_rowptr[i] = sh[t] - d;
    if (t == 255) g_bsum[b] = sh[255];
}

__global__ void __launch_bounds__(512)
scan2_kernel() {
    __shared__ int sh[512];
    int t = threadIdx.x;
    int v = (t < NBLK) ? g_bsum[t] : 0;
    sh[t] = v;
    __syncthreads();
    for (int o = 1; o < 512; o <<= 1) {
        int u = (t >= o) ? sh[t - o] : 0;
        __syncthreads();
        sh[t] += u;
        __syncthreads();
    }
    g_bsum[t] = sh[t] - v;
}

__global__ void __launch_bounds__(256)
scan3_kernel() {
    int t = threadIdx.x, b = blockIdx.x;
    int i = b * 256 + t;
    if (i < NN) {
        int r = g_rowptr[i] + g_bsum[b];
        g_rowptr[i] = r;
        g_cnt[i] = r;
    }
    if (b == 0 && t == 0) g_rowptr[NN] = EE;
}

__global__ void __launch_bounds__(256)
scatter_kernel(const int* __restrict__ src, const int* __restrict__ dst) {
    int e = blockIdx.x * blockDim.x + threadIdx.x;
    if (e >= EE) return;
    int p = atomicAdd(&g_cnt[dst[e]], 1);
    g_csrc[p] = src[e];
}

// ====================== SGEMM (+ optional fused el/er epilogue) ======================
// BMx(TBN) tile, BK=16, 256 threads, 8x(TBN/16) per thread, double-buffered, FFMA2.
// B duplicated in smem: col n at (n%CPT)*32 + (n/CPT)*2 (+dup) -> direct LDS.64 pair.
template<int TBN>
__device__ __forceinline__ void load_tile(
    const float* __restrict__ A, const float* __restrict__ B,
    int M, int N, int K, int row0, int col0, int k0, int tid,
    float (* __restrict__ As)[BM + 2], float* __restrict__ Bs) {
    constexpr int CPT = TBN / 16;
    constexpr int BROW = CPT * 32;
    #pragma unroll
    for (int t = 0; t < 2; t++) {
        int fi = tid + t * 256;
        int row = fi >> 2, kq = fi & 3;
        int gr = row0 + row;
        float4 v = make_float4(0.f, 0.f, 0.f, 0.f);
        if (gr < M) v = *(const float4*)&A[(long)gr * K + k0 + kq * 4];
        As[kq * 4 + 0][row] = v.x;
        As[kq * 4 + 1][row] = v.y;
        As[kq * 4 + 2][row] = v.z;
        As[kq * 4 + 3][row] = v.w;
    }
    #pragma unroll
    for (int t = 0; t < TBN / 64; t++) {
        int fi = tid + t * 256;
        int krow = fi / (TBN / 4), nq = fi % (TBN / 4);
        int gc = col0 + nq * 4;
        float4 v = make_float4(0.f, 0.f, 0.f, 0.f);
        if (gc < N) v = *(const float4*)&B[(long)(k0 + krow) * N + gc];
        float vv[4] = {v.x, v.y, v.z, v.w};
        #pragma unroll
        for (int e = 0; e < 4; e++) {
            int n = nq * 4 + e;
            int addr = (n % CPT) * 32 + (n / CPT) * 2;
            *(float2*)&Bs[krow * BROW + addr] = make_float2(vv[e], vv[e]);
        }
    }
}

template<int TBN, bool FUSE_ELR>
__global__ void __launch_bounds__(256)
sgemm_kernel(const float* __restrict__ A, const float* __restrict__ B,
             int M, int N, int K,
             const float* __restrict__ al, const float* __restrict__ ar) {
    constexpr int CPT = TBN / 16;
    constexpr int BROW = CPT * 32;
    __shared__ __align__(16) float As[2][BK][BM + 2];
    __shared__ __align__(16) float Bs[2][BK * BROW];
    const int tid = threadIdx.x;
    const int tx = tid & 15;
    const int ty = tid >> 4;
    const int row0 = blockIdx.x * BM;
    const int col0 = blockIdx.y * TBN;

    unsigned long long acc[4][CPT];
    #pragma unroll
    for (int r = 0; r < 4; r++)
        #pragma unroll
        for (int j = 0; j < CPT; j++) acc[r][j] = 0ull;

    load_tile<TBN>(A, B, M, N, K, row0, col0, 0, tid, As[0], Bs[0]);
    __syncthreads();

    int buf = 0;
    for (int k0 = 0; k0 < K; k0 += BK) {
        if (k0 + BK < K)
            load_tile<TBN>(A, B, M, N, K, row0, col0, k0 + BK, tid, As[buf ^ 1], Bs[buf ^ 1]);
        #pragma unroll
        for (int kk = 0; kk < BK; kk++) {
            unsigned long long ap[4];
            #pragma unroll
            for (int r = 0; r < 4; r++)
                ap[r] = *(const unsigned long long*)&As[buf][kk][ty * 8 + r * 2];
            unsigned long long bd[CPT];
            #pragma unroll
            for (int j = 0; j < CPT; j++)
                bd[j] = *(const unsigned long long*)&Bs[buf][kk * BROW + j * 32 + tx * 2];
            #pragma unroll
            for (int r = 0; r < 4; r++)
                #pragma unroll
                for (int j = 0; j < CPT; j++)
                    asm("fma.rn.f32x2 %0, %1, %2, %0;"
                        : "+l"(acc[r][j]) : "l"(ap[r]), "l"(bd[j]));
        }
        __syncthreads();
        buf ^= 1;
    }

    const int cbase = col0 + tx * CPT;
    // attention vectors for my 8 columns (only used when FUSE_ELR; N==128 layout: al[col])
    float alv[CPT], arv[CPT];
    if (FUSE_ELR) {
        #pragma unroll
        for (int j = 0; j < CPT; j++) { alv[j] = al[cbase + j]; arv[j] = ar[cbase + j]; }
    }

    #pragma unroll
    for (int r = 0; r < 4; r++) {
        float lo[CPT], hi[CPT];
        #pragma unroll
        for (int j = 0; j < CPT; j++)
            asm("mov.b64 {%0, %1}, %2;" : "=f"(lo[j]), "=f"(hi[j]) : "l"(acc[r][j]));
        int gr0 = row0 + ty * 8 + 2 * r;
        #pragma unroll
        for (int p = 0; p < 2; p++) {
            int gr = gr0 + p;
            const float* c = p ? hi : lo;
            if (gr < M) {
                if (cbase + CPT - 1 < N) {
                    #pragma unroll
                    for (int q = 0; q < CPT / 4; q++)
                        *(float4*)&g_feat[(long)gr * N + cbase + q * 4] =
                            make_float4(c[q * 4], c[q * 4 + 1], c[q * 4 + 2], c[q * 4 + 3]);
                } else {
                    for (int jj = 0; jj < CPT; jj++)
                        if (cbase + jj < N) g_feat[(long)gr * N + cbase + jj] = c[jj];
                }
            }
            if (FUSE_ELR) {
                // partial dot over my 8 cols; reduce across tx groups of 4 (one head = 4 tx)
                float pel = 0.f, per = 0.f;
                #pragma unroll
                for (int j = 0; j < CPT; j++) { pel += c[j] * alv[j]; per += c[j] * arv[j]; }
                pel += __shfl_xor_sync(0xffffffffu, pel, 1);
                per += __shfl_xor_sync(0xffffffffu, per, 1);
                pel += __shfl_xor_sync(0xffffffffu, pel, 2);
                per += __shfl_xor_sync(0xffffffffu, per, 2);
                if ((tx & 3) == 0 && gr < M) {
                    int h = tx >> 2;
                    g_el[gr * 4 + h] = pel;
                    g_er[gr * 4 + h] = per;
                }
            }
        }
    }
}

// ====================== el/er per (node, head) — layer 3 only ======================
__global__ void __launch_bounds__(256)
elr_kernel(const float* __restrict__ al, const float* __restrict__ ar, int od) {
    int idx = blockIdx.x * blockDim.x + threadIdx.x;
    if (idx >= NN * HH) return;
    int n = idx >> 2, h = idx & 3;
    const float* f = g_feat + (long)n * HH * od + h * od;
    const float* alh = al + h * od;
    const float* arh = ar + h * od;
    float sl = 0.f, sr = 0.f;
    for (int d = 0; d < od; d++) { float v = f[d]; sl += v * alh[d]; sr += v * arh[d]; }
    g_el[idx] = sl;
    g_er[idx] = sr;
}

__device__ __forceinline__ float lrelu(float v) { return v > 0.f ? v : NEG_SLOPE * v; }

__device__ __forceinline__ float pick4(float4 v, int h) {
    float ab = (h & 1) ? v.y : v.x;
    float cd = (h & 1) ? v.w : v.z;
    return (h & 2) ? cd : ab;
}

// ====================== FUSED softmax+aggregation F=128 (warp per node) ======================
__global__ void __launch_bounds__(256)
agg128_fused(const float* __restrict__ bias) {
    __shared__ float4 sh_ex [8][32];
    __shared__ int    sh_src[8][32];
    int node = (blockIdx.x * blockDim.x + threadIdx.x) >> 5;
    int lane = threadIdx.x & 31;
    int wid = threadIdx.x >> 5;
    if (node >= NN) return;
    int r0 = g_rowptr[node], r1 = g_rowptr[node + 1];
    const int head = lane >> 3;

    float4 erd = *(const float4*)&g_er[node * 4];

    float den0 = 0.f, den1 = 0.f, den2 = 0.f, den3 = 0.f;
    float4 acc = {0.f, 0.f, 0.f, 0.f};
    for (int c0 = r0; c0 < r1; c0 += 32) {
        int n = min(32, r1 - c0);
        if (lane < n) {
            int s = g_csrc[c0 + lane];
            float4 ev = *(const float4*)&g_el[s * 4];
            float4 ex;
            ex.x = __expf(lrelu(ev.x + erd.x));
            ex.y = __expf(lrelu(ev.y + erd.y));
            ex.z = __expf(lrelu(ev.z + erd.z));
            ex.w = __expf(lrelu(ev.w + erd.w));
            sh_ex[wid][lane] = ex;
            sh_src[wid][lane] = s;
            den0 += ex.x; den1 += ex.y; den2 += ex.z; den3 += ex.w;
        }
        __syncwarp();
        int k = 0;
        #pragma unroll 1
        for (; k + 7 < n; k += 8) {
            float a[8]; int s[8];
            #pragma unroll
            for (int q = 0; q < 8; q++) {
                a[q] = pick4(sh_ex[wid][k + q], head);
                s[q] = sh_src[wid][k + q];
            }
            float4 f[8];
            #pragma unroll
            for (int q = 0; q < 8; q++)
                f[q] = *(const float4*)&g_feat[(long)s[q] * 128 + lane * 4];
            #pragma unroll
            for (int q = 0; q < 8; q++) {
                acc.x += a[q] * f[q].x;
                acc.y += a[q] * f[q].y;
                acc.z += a[q] * f[q].z;
                acc.w += a[q] * f[q].w;
            }
        }
        for (; k < n; k++) {
            float a = pick4(sh_ex[wid][k], head);
            int s = sh_src[wid][k];
            float4 f = *(const float4*)&g_feat[(long)s * 128 + lane * 4];
            acc.x += a * f.x; acc.y += a * f.y; acc.z += a * f.z; acc.w += a * f.w;
        }
        __syncwarp();
    }
    #pragma unroll
    for (int o = 16; o > 0; o >>= 1) {
        den0 += __shfl_xor_sync(0xffffffffu, den0, o);
        den1 += __shfl_xor_sync(0xffffffffu, den1, o);
        den2 += __shfl_xor_sync(0xffffffffu, den2, o);
        den3 += __shfl_xor_sync(0xffffffffu, den3, o);
    }
    float4 dv = make_float4(den0, den1, den2, den3);
    float dh = pick4(dv, head);
    float invh = (dh > 0.f) ? 1.f / dh : 0.f;
    float4 b = *(const float4*)&bias[lane * 4];
    acc.x = fmaxf(acc.x * invh + b.x, 0.f);
    acc.y = fmaxf(acc.y * invh + b.y, 0.f);
    acc.z = fmaxf(acc.z * invh + b.z, 0.f);
    acc.w = fmaxf(acc.w * invh + b.w, 0.f);
    *(float4*)&g_out[(long)node * 128 + lane * 4] = acc;
}

// ====================== FUSED softmax+aggregation F=188 (warp per node) ======================
__global__ void __launch_bounds__(256)
agg188_fused() {
    __shared__ float4 sh_ex [8][32];
    __shared__ int    sh_src[8][32];
    int node = (blockIdx.x * blockDim.x + threadIdx.x) >> 5;
    int lane = threadIdx.x & 31;
    int wid = threadIdx.x >> 5;
    if (node >= NN) return;
    int r0 = g_rowptr[node], r1 = g_rowptr[node + 1];

    float4 erd = *(const float4*)&g_er[node * 4];

    float den0 = 0.f, den1 = 0.f, den2 = 0.f, den3 = 0.f;
    float acc[6] = {0.f, 0.f, 0.f, 0.f, 0.f, 0.f};
    int headk[6];
    #pragma unroll
    for (int k = 0; k < 6; k++) headk[k] = (lane + 32 * k) / CC;

    for (int c0 = r0; c0 < r1; c0 += 32) {
        int n = min(32, r1 - c0);
        if (lane < n) {
            int s = g_csrc[c0 + lane];
            float4 ev = *(const float4*)&g_el[s * 4];
            float4 ex;
            ex.x = __expf(lrelu(ev.x + erd.x));
            ex.y = __expf(lrelu(ev.y + erd.y));
            ex.z = __expf(lrelu(ev.z + erd.z));
            ex.w = __expf(lrelu(ev.w + erd.w));
            sh_ex[wid][lane] = ex;
            sh_src[wid][lane] = s;
            den0 += ex.x; den1 += ex.y; den2 += ex.z; den3 += ex.w;
        }
        __syncwarp();
        #pragma unroll 1
        for (int k = 0; k < n; k++) {
            float4 ex4 = sh_ex[wid][k];
            int s = sh_src[wid][k];
            const float* fs = g_feat + (long)s * 188;
            #pragma unroll
            for (int q = 0; q < 6; q++) {
                int j = lane + 32 * q;
                if (j < 188) acc[q] += pick4(ex4, headk[q]) * fs[j];
            }
        }
        __syncwarp();
    }
    #pragma unroll
    for (int o = 16; o > 0; o >>= 1) {
        den0 += __shfl_xor_sync(0xffffffffu, den0, o);
        den1 += __shfl_xor_sync(0xffffffffu, den1, o);
        den2 += __shfl_xor_sync(0xffffffffu, den2, o);
        den3 += __shfl_xor_sync(0xffffffffu, den3, o);
    }
    float4 dv = make_float4(den0, den1, den2, den3);
    float* op = g_out + (long)node * 188;
    #pragma unroll
    for (int q = 0; q < 6; q++) {
        int j = lane + 32 * q;
        if (j < 188) {
            float dh = pick4(dv, headk[q]);
            float invh = (dh > 0.f) ? 1.f / dh : 0.f;
            op[j] = acc[q] * invh;
        }
    }
}

// ====================== final: head-mean (+bias) + log_softmax (warp per node) ======================
__global__ void __launch_bounds__(256)
final_kernel(const float* __restrict__ b3, float* __restrict__ y) {
    int node = (blockIdx.x * blockDim.x + threadIdx.x) >> 5;
    int lane = threadIdx.x & 31;
    if (node >= NN) return;
    const float* row = g_out + (long)node * HH * CC;

    float a0 = 0.f, a1 = 0.f;
    float v0 = -CUDART_INF_F, v1 = -CUDART_INF_F;
    if (lane < CC) {
        float sum = 0.f;
        #pragma unroll
        for (int h = 0; h < HH; h++) sum += row[h * CC + lane] + b3[h * CC + lane];
        a0 = sum * 0.25f; v0 = a0;
    }
    int c1 = lane + 32;
    if (c1 < CC) {
        float sum = 0.f;
        #pragma unroll
        for (int h = 0; h < HH; h++) sum += row[h * CC + c1] + b3[h * CC + c1];
        a1 = sum * 0.25f; v1 = a1;
    }
    float mx = fmaxf(v0, v1);
    #pragma unroll
    for (int o = 16; o > 0; o >>= 1) mx = fmaxf(mx, __shfl_xor_sync(0xffffffffu, mx, o));
    float s = 0.f;
    if (lane < CC) s += __expf(a0 - mx);
    if (c1 < CC)   s += __expf(a1 - mx);
    #pragma unroll
    for (int o = 16; o > 0; o >>= 1) s += __shfl_xor_sync(0xffffffffu, s, o);
    float lse = logf(s);
    if (lane < CC) y[(long)node * CC + lane] = a0 - mx - lse;
    if (c1 < CC)   y[(long)node * CC + c1] = a1 - mx - lse;
}

// ====================== host driver ======================
extern "C" void kernel_launch(void* const* d_in, const int* in_sizes, int n_in,
                              void* d_out, int out_size) {
    const float* x   = (const float*)d_in[0];
    const int*   src = (const int*)  d_in[1];
    const int*   dst = (const int*)  d_in[2];
    const float* W1  = (const float*)d_in[3];
    const float* al1 = (const float*)d_in[4];
    const float* ar1 = (const float*)d_in[5];
    const float* b1  = (const float*)d_in[6];
    const float* W2  = (const float*)d_in[7];
    const float* al2 = (const float*)d_in[8];
    const float* ar2 = (const float*)d_in[9];
    const float* b2  = (const float*)d_in[10];
    const float* W3  = (const float*)d_in[11];
    const float* al3 = (const float*)d_in[12];
    const float* ar3 = (const float*)d_in[13];
    const float* b3  = (const float*)d_in[14];
    float* y = (float*)d_out;

    static float* outb = nullptr;
    static cudaStream_t s2 = nullptr;
    static cudaEvent_t evFork = nullptr, evJoin = nullptr;
    if (!outb) {
        cudaGetSymbolAddress((void**)&outb, g_out);
        cudaStreamCreateWithFlags(&s2, cudaStreamNonBlocking);
        cudaEventCreateWithFlags(&evFork, cudaEventDisableTiming);
        cudaEventCreateWithFlags(&evJoin, cudaEventDisableTiming);
    }

    const int TB = 256;
    const int nodeWarpGrid = (NN + 7) / 8;

    // ---- fork: CSR build on side stream, overlapped with layer-1 gemm ----
    cudaEventRecord(evFork, 0);
    cudaStreamWaitEvent(s2, evFork, 0);
    zero_deg_kernel<<<(NN + TB - 1) / TB, TB, 0, s2>>>();
    hist_kernel<<<(EE + TB - 1) / TB, TB, 0, s2>>>(dst);
    scan1_kernel<<<NBLK, TB, 0, s2>>>();
    scan2_kernel<<<1, 512, 0, s2>>>();
    scan3_kernel<<<NBLK, TB, 0, s2>>>();
    scatter_kernel<<<(EE + TB - 1) / TB, TB, 0, s2>>>(src, dst);
    cudaEventRecord(evJoin, s2);

    // ---- layer 1 gemm (+fused el/er) on main stream ----
    {
        dim3 gg((NN + BM - 1) / BM, 1);
        sgemm_kernel<128, true><<<gg, TB>>>(x, W1, NN, 128, F_IN, al1, ar1);
    }
    // ---- join: aggregation needs the CSR ----
    cudaStreamWaitEvent(0, evJoin, 0);
    agg128_fused<<<nodeWarpGrid, TB>>>(b1);

    // ---- layer 2 ----
    {
        dim3 gg((NN + BM - 1) / BM, 1);
        sgemm_kernel<128, true><<<gg, TB>>>(outb, W2, NN, 128, 128, al2, ar2);
        agg128_fused<<<nodeWarpGrid, TB>>>(b2);
    }
    // ---- layer 3 (BN=64 tiles; separate elr; bias fused into final) ----
    {
        dim3 gg((NN + BM - 1) / BM, (188 + 63) / 64);
        sgemm_kernel<64, false><<<gg, TB>>>(outb, W3, NN, 188, 128, nullptr, nullptr);
        elr_kernel<<<(NN * HH + TB - 1) / TB, TB>>>(al3, ar3, CC);
        agg188_fused<<<nodeWarpGrid, TB>>>();
    }
    // ---- head-mean + bias + log_softmax ----
    final_kernel<<<(NN + 7) / 8, TB>>>(b3, y);
}

// round 13
// speedup vs baseline: 1.7699x; 1.2970x over previous
#include <cuda_runtime.h>
#include <cuda_bf16.h>
#include <math_constants.h>

#define NN 100000
#define EE 1600000
#define F_IN 256
#define HH 4
#define DD 32
#define CC 47
#define NP3 48                    // padded class count (float4-aligned rows)
#define NEG_SLOPE 0.2f

#define BM 128
#define BK 16
#define NBLK ((NN + 255) / 256)   // 391

// ---------------- scratch (__device__ globals; no allocation) ----------------
__device__ float g_feat [NN * HH * CC];
__device__ float g_out  [NN * HH * CC];
__device__ float g_el   [NN * HH];
__device__ float g_er   [NN * HH];
__device__ float g_el3  [NN * HH];       // layer-3 logits (separate: race-free)
__device__ float g_er3  [NN * HH];
__device__ int   g_deg  [NN];
__device__ int   g_cnt  [NN];
__device__ int   g_rowptr[NN + 1];
__device__ int   g_csrc [EE];
__device__ int   g_bsum [512];
// layer-3 derived operands
__device__ float g_P3 [128 * 4];          // W3 @ al3 (per head)
__device__ float g_Q3 [128 * 4];          // W3 @ ar3
__device__ __align__(16) float g_W3m[128 * NP3];  // mean of W3 head blocks, padded
__device__ float g_b3m[CC];               // mean of b3 head blocks

// ====================== CSR build + layer-3 prep (side stream) ======================
__global__ void __launch_bounds__(256)
zero_deg_kernel() {
    int i = blockIdx.x * blockDim.x + threadIdx.x;
    if (i < NN) g_deg[i] = 0;
}

__global__ void __launch_bounds__(256)
hist_kernel(const int* __restrict__ dst) {
    int e = blockIdx.x * blockDim.x + threadIdx.x;
    if (e < EE) atomicAdd(&g_deg[dst[e]], 1);
}

__global__ void __launch_bounds__(256)
scan1_kernel() {
    __shared__ int sh[256];
    int t = threadIdx.x, b = blockIdx.x;
    int i = b * 256 + t;
    int d = (i < NN) ? g_deg[i] : 0;
    sh[t] = d;
    __syncthreads();
    for (int o = 1; o < 256; o <<= 1) {
        int v = (t >= o) ? sh[t - o] : 0;
        __syncthreads();
        sh[t] += v;
        __syncthreads();
    }
    if (i < NN) g_rowptr[i] = sh[t] - d;
    if (t == 255) g_bsum[b] = sh[255];
}

__global__ void __launch_bounds__(512)
scan2_kernel() {
    __shared__ int sh[512];
    int t = threadIdx.x;
    int v = (t < NBLK) ? g_bsum[t] : 0;
    sh[t] = v;
    __syncthreads();
    for (int o = 1; o < 512; o <<= 1) {
        int u = (t >= o) ? sh[t - o] : 0;
        __syncthreads();
        sh[t] += u;
        __syncthreads();
    }
    g_bsum[t] = sh[t] - v;
}

__global__ void __launch_bounds__(256)
scan3_kernel() {
    int t = threadIdx.x, b = blockIdx.x;
    int i = b * 256 + t;
    if (i < NN) {
        int r = g_rowptr[i] + g_bsum[b];
        g_rowptr[i] = r;
        g_cnt[i] = r;
    }
    if (b == 0 && t == 0) g_rowptr[NN] = EE;
}

__global__ void __launch_bounds__(256)
scatter_kernel(const int* __restrict__ src, const int* __restrict__ dst) {
    int e = blockIdx.x * blockDim.x + threadIdx.x;
    if (e >= EE) return;
    int p = atomicAdd(&g_cnt[dst[e]], 1);
    g_csrc[p] = src[e];
}

// P3/Q3 = W3 @ al3/ar3 per head; W3m (padded to NP3) / b3m = head means
__global__ void __launch_bounds__(256)
prep3_kernel(const float* __restrict__ W3, const float* __restrict__ al3,
             const float* __restrict__ ar3, const float* __restrict__ b3) {
    int i = blockIdx.x * blockDim.x + threadIdx.x;
    if (i < 128 * NP3) {
        int k = i / NP3, c = i % NP3;
        const float* w = W3 + k * (HH * CC);
        g_W3m[k * NP3 + c] = (c < CC)
            ? 0.25f * (w[c] + w[CC + c] + w[2 * CC + c] + w[3 * CC + c])
            : 0.f;
    }
    if (i < 128 * HH) {
        int k = i >> 2, h = i & 3;
        const float* w = W3 + k * (HH * CC) + h * CC;
        const float* a = al3 + h * CC;
        const float* r = ar3 + h * CC;
        float s = 0.f, t = 0.f;
        for (int c = 0; c < CC; c++) { s += w[c] * a[c]; t += w[c] * r[c]; }
        g_P3[i] = s;
        g_Q3[i] = t;
    }
    if (i < CC) g_b3m[i] = 0.25f * (b3[i] + b3[CC + i] + b3[2 * CC + i] + b3[3 * CC + i]);
}

// ====================== SGEMM (+ optional fused el/er epilogue) ======================
// NOTE: requires N % 4 == 0 (float4 loads/stores on B and C rows).
template<int TBN>
__device__ __forceinline__ void load_tile(
    const float* __restrict__ A, const float* __restrict__ B,
    int M, int N, int K, int row0, int col0, int k0, int tid,
    float (* __restrict__ As)[BM + 2], float* __restrict__ Bs) {
    constexpr int CPT = TBN / 16;
    constexpr int BROW = CPT * 32;
    #pragma unroll
    for (int t = 0; t < 2; t++) {
        int fi = tid + t * 256;
        int row = fi >> 2, kq = fi & 3;
        int gr = row0 + row;
        float4 v = make_float4(0.f, 0.f, 0.f, 0.f);
        if (gr < M) v = *(const float4*)&A[(long)gr * K + k0 + kq * 4];
        As[kq * 4 + 0][row] = v.x;
        As[kq * 4 + 1][row] = v.y;
        As[kq * 4 + 2][row] = v.z;
        As[kq * 4 + 3][row] = v.w;
    }
    #pragma unroll
    for (int t = 0; t < TBN / 64; t++) {
        int fi = tid + t * 256;
        int krow = fi / (TBN / 4), nq = fi % (TBN / 4);
        int gc = col0 + nq * 4;
        float4 v = make_float4(0.f, 0.f, 0.f, 0.f);
        if (gc + 3 < N) v = *(const float4*)&B[(long)(k0 + krow) * N + gc];
        float vv[4] = {v.x, v.y, v.z, v.w};
        #pragma unroll
        for (int e = 0; e < 4; e++) {
            int n = nq * 4 + e;
            int addr = (n % CPT) * 32 + (n / CPT) * 2;
            *(float2*)&Bs[krow * BROW + addr] = make_float2(vv[e], vv[e]);
        }
    }
}

template<int TBN, bool FUSE_ELR>
__global__ void __launch_bounds__(256)
sgemm_kernel(const float* __restrict__ A, const float* __restrict__ B,
             float* __restrict__ C, int M, int N, int K,
             const float* __restrict__ al, const float* __restrict__ ar) {
    constexpr int CPT = TBN / 16;
    constexpr int BROW = CPT * 32;
    __shared__ __align__(16) float As[2][BK][BM + 2];
    __shared__ __align__(16) float Bs[2][BK * BROW];
    const int tid = threadIdx.x;
    const int tx = tid & 15;
    const int ty = tid >> 4;
    const int row0 = blockIdx.x * BM;
    const int col0 = blockIdx.y * TBN;

    unsigned long long acc[4][CPT];
    #pragma unroll
    for (int r = 0; r < 4; r++)
        #pragma unroll
        for (int j = 0; j < CPT; j++) acc[r][j] = 0ull;

    load_tile<TBN>(A, B, M, N, K, row0, col0, 0, tid, As[0], Bs[0]);
    __syncthreads();

    int buf = 0;
    for (int k0 = 0; k0 < K; k0 += BK) {
        if (k0 + BK < K)
            load_tile<TBN>(A, B, M, N, K, row0, col0, k0 + BK, tid, As[buf ^ 1], Bs[buf ^ 1]);
        #pragma unroll
        for (int kk = 0; kk < BK; kk++) {
            unsigned long long ap[4];
            #pragma unroll
            for (int r = 0; r < 4; r++)
                ap[r] = *(const unsigned long long*)&As[buf][kk][ty * 8 + r * 2];
            unsigned long long bd[CPT];
            #pragma unroll
            for (int j = 0; j < CPT; j++)
                bd[j] = *(const unsigned long long*)&Bs[buf][kk * BROW + j * 32 + tx * 2];
            #pragma unroll
            for (int r = 0; r < 4; r++)
                #pragma unroll
                for (int j = 0; j < CPT; j++)
                    asm("fma.rn.f32x2 %0, %1, %2, %0;"
                        : "+l"(acc[r][j]) : "l"(ap[r]), "l"(bd[j]));
        }
        __syncthreads();
        buf ^= 1;
    }

    const int cbase = col0 + tx * CPT;
    float alv[CPT], arv[CPT];
    if (FUSE_ELR) {
        #pragma unroll
        for (int j = 0; j < CPT; j++) { alv[j] = al[cbase + j]; arv[j] = ar[cbase + j]; }
    }

    #pragma unroll
    for (int r = 0; r < 4; r++) {
        float lo[CPT], hi[CPT];
        #pragma unroll
        for (int j = 0; j < CPT; j++)
            asm("mov.b64 {%0, %1}, %2;" : "=f"(lo[j]), "=f"(hi[j]) : "l"(acc[r][j]));
        int gr0 = row0 + ty * 8 + 2 * r;
        #pragma unroll
        for (int p = 0; p < 2; p++) {
            int gr = gr0 + p;
            const float* c = p ? hi : lo;
            if (gr < M) {
                #pragma unroll
                for (int q = 0; q < CPT / 4; q++)
                    if (cbase + q * 4 + 3 < N)
                        *(float4*)&C[(long)gr * N + cbase + q * 4] =
                            make_float4(c[q * 4], c[q * 4 + 1], c[q * 4 + 2], c[q * 4 + 3]);
            }
            if (FUSE_ELR) {
                float pel = 0.f, per = 0.f;
                #pragma unroll
                for (int j = 0; j < CPT; j++) { pel += c[j] * alv[j]; per += c[j] * arv[j]; }
                pel += __shfl_xor_sync(0xffffffffu, pel, 1);
                per += __shfl_xor_sync(0xffffffffu, per, 1);
                pel += __shfl_xor_sync(0xffffffffu, pel, 2);
                per += __shfl_xor_sync(0xffffffffu, per, 2);
                if ((tx & 3) == 0 && gr < M) {
                    int h = tx >> 2;
                    g_el[gr * 4 + h] = pel;
                    g_er[gr * 4 + h] = per;
                }
            }
        }
    }
}

__device__ __forceinline__ float lrelu(float v) { return v > 0.f ? v : NEG_SLOPE * v; }

__device__ __forceinline__ float pick4(float4 v, int h) {
    float ab = (h & 1) ? v.y : v.x;
    float cd = (h & 1) ? v.w : v.z;
    return (h & 2) ? cd : ab;
}

// ====================== FUSED softmax+aggregation, 128-wide (warp per node) ======================
template<bool BIAS_RELU, bool EMIT3>
__global__ void __launch_bounds__(256)
agg128_fused(const float* __restrict__ feat, float* __restrict__ out,
             const float* __restrict__ el, const float* __restrict__ er,
             const float* __restrict__ bias) {
    __shared__ float4 sh_ex [8][32];
    __shared__ int    sh_src[8][32];
    int node = (blockIdx.x * blockDim.x + threadIdx.x) >> 5;
    int lane = threadIdx.x & 31;
    int wid = threadIdx.x >> 5;
    if (node >= NN) return;
    int r0 = g_rowptr[node], r1 = g_rowptr[node + 1];
    const int head = lane >> 3;

    float4 erd = *(const float4*)&er[node * 4];

    float den0 = 0.f, den1 = 0.f, den2 = 0.f, den3 = 0.f;
    float4 acc = {0.f, 0.f, 0.f, 0.f};
    for (int c0 = r0; c0 < r1; c0 += 32) {
        int n = min(32, r1 - c0);
        if (lane < n) {
            int s = g_csrc[c0 + lane];
            float4 ev = *(const float4*)&el[s * 4];
            float4 ex;
            ex.x = __expf(lrelu(ev.x + erd.x));
            ex.y = __expf(lrelu(ev.y + erd.y));
            ex.z = __expf(lrelu(ev.z + erd.z));
            ex.w = __expf(lrelu(ev.w + erd.w));
            sh_ex[wid][lane] = ex;
            sh_src[wid][lane] = s;
            den0 += ex.x; den1 += ex.y; den2 += ex.z; den3 += ex.w;
        }
        __syncwarp();
        int k = 0;
        #pragma unroll 1
        for (; k + 7 < n; k += 8) {
            float a[8]; int s[8];
            #pragma unroll
            for (int q = 0; q < 8; q++) {
                a[q] = pick4(sh_ex[wid][k + q], head);
                s[q] = sh_src[wid][k + q];
            }
            float4 f[8];
            #pragma unroll
            for (int q = 0; q < 8; q++)
                f[q] = *(const float4*)&feat[(long)s[q] * 128 + lane * 4];
            #pragma unroll
            for (int q = 0; q < 8; q++) {
                acc.x += a[q] * f[q].x;
                acc.y += a[q] * f[q].y;
                acc.z += a[q] * f[q].z;
                acc.w += a[q] * f[q].w;
            }
        }
        for (; k < n; k++) {
            float a = pick4(sh_ex[wid][k], head);
            int s = sh_src[wid][k];
            float4 f = *(const float4*)&feat[(long)s * 128 + lane * 4];
            acc.x += a * f.x; acc.y += a * f.y; acc.z += a * f.z; acc.w += a * f.w;
        }
        __syncwarp();
    }
    #pragma unroll
    for (int o = 16; o > 0; o >>= 1) {
        den0 += __shfl_xor_sync(0xffffffffu, den0, o);
        den1 += __shfl_xor_sync(0xffffffffu, den1, o);
        den2 += __shfl_xor_sync(0xffffffffu, den2, o);
        den3 += __shfl_xor_sync(0xffffffffu, den3, o);
    }
    float4 dv = make_float4(den0, den1, den2, den3);
    float dh = pick4(dv, head);
    float invh = (dh > 0.f) ? 1.f / dh : 0.f;
    acc.x *= invh; acc.y *= invh; acc.z *= invh; acc.w *= invh;
    if (BIAS_RELU) {
        float4 b = *(const float4*)&bias[lane * 4];
        acc.x = fmaxf(acc.x + b.x, 0.f);
        acc.y = fmaxf(acc.y + b.y, 0.f);
        acc.z = fmaxf(acc.z + b.z, 0.f);
        acc.w = fmaxf(acc.w + b.w, 0.f);
    }
    *(float4*)&out[(long)node * 128 + lane * 4] = acc;

    if (EMIT3) {
        float e0 = 0.f, e1 = 0.f, e2 = 0.f, e3 = 0.f;
        float q0 = 0.f, q1 = 0.f, q2 = 0.f, q3 = 0.f;
        float ov[4] = {acc.x, acc.y, acc.z, acc.w};
        #pragma unroll
        for (int q = 0; q < 4; q++) {
            float4 p = ((const float4*)g_P3)[lane * 4 + q];
            float4 w = ((const float4*)g_Q3)[lane * 4 + q];
            e0 += ov[q] * p.x; e1 += ov[q] * p.y; e2 += ov[q] * p.z; e3 += ov[q] * p.w;
            q0 += ov[q] * w.x; q1 += ov[q] * w.y; q2 += ov[q] * w.z; q3 += ov[q] * w.w;
        }
        #pragma unroll
        for (int o = 16; o > 0; o >>= 1) {
            e0 += __shfl_xor_sync(0xffffffffu, e0, o);
            e1 += __shfl_xor_sync(0xffffffffu, e1, o);
            e2 += __shfl_xor_sync(0xffffffffu, e2, o);
            e3 += __shfl_xor_sync(0xffffffffu, e3, o);
            q0 += __shfl_xor_sync(0xffffffffu, q0, o);
            q1 += __shfl_xor_sync(0xffffffffu, q1, o);
            q2 += __shfl_xor_sync(0xffffffffu, q2, o);
            q3 += __shfl_xor_sync(0xffffffffu, q3, o);
        }
        if (lane == 0) {
            *(float4*)&g_el3[node * 4] = make_float4(e0, e1, e2, e3);
            *(float4*)&g_er3[node * 4] = make_float4(q0, q1, q2, q3);
        }
    }
}

// ====================== final: +b3m + log_softmax over 47 (warp per node; stride NP3) ======================
__global__ void __launch_bounds__(256)
final47_kernel(float* __restrict__ y) {
    int node = (blockIdx.x * blockDim.x + threadIdx.x) >> 5;
    int lane = threadIdx.x & 31;
    if (node >= NN) return;
    const float* row = g_out + (long)node * NP3;

    float a0 = row[lane] + g_b3m[lane];                 // lanes 0..31 all < 47
    float a1 = 0.f, v1 = -CUDART_INF_F;
    int c1 = lane + 32;
    if (c1 < CC) { a1 = row[c1] + g_b3m[c1]; v1 = a1; }
    float mx = fmaxf(a0, v1);
    #pragma unroll
    for (int o = 16; o > 0; o >>= 1) mx = fmaxf(mx, __shfl_xor_sync(0xffffffffu, mx, o));
    float s = __expf(a0 - mx);
    if (c1 < CC) s += __expf(a1 - mx);
    #pragma unroll
    for (int o = 16; o > 0; o >>= 1) s += __shfl_xor_sync(0xffffffffu, s, o);
    float lse = logf(s);
    y[(long)node * CC + lane] = a0 - mx - lse;
    if (c1 < CC) y[(long)node * CC + c1] = a1 - mx - lse;
}

// ====================== host driver ======================
extern "C" void kernel_launch(void* const* d_in, const int* in_sizes, int n_in,
                              void* d_out, int out_size) {
    const float* x   = (const float*)d_in[0];
    const int*   src = (const int*)  d_in[1];
    const int*   dst = (const int*)  d_in[2];
    const float* W1  = (const float*)d_in[3];
    const float* al1 = (const float*)d_in[4];
    const float* ar1 = (const float*)d_in[5];
    const float* b1  = (const float*)d_in[6];
    const float* W2  = (const float*)d_in[7];
    const float* al2 = (const float*)d_in[8];
    const float* ar2 = (const float*)d_in[9];
    const float* b2  = (const float*)d_in[10];
    const float* W3  = (const float*)d_in[11];
    const float* al3 = (const float*)d_in[12];
    const float* ar3 = (const float*)d_in[13];
    const float* b3  = (const float*)d_in[14];
    float* y = (float*)d_out;

    static float *outb = nullptr, *featb = nullptr, *elb = nullptr, *erb = nullptr;
    static float *el3b = nullptr, *er3b = nullptr, *w3mb = nullptr;
    static cudaStream_t s2 = nullptr;
    static cudaEvent_t evFork = nullptr, evJoin = nullptr;
    if (!outb) {
        cudaGetSymbolAddress((void**)&outb,  g_out);
        cudaGetSymbolAddress((void**)&featb, g_feat);
        cudaGetSymbolAddress((void**)&elb,   g_el);
        cudaGetSymbolAddress((void**)&erb,   g_er);
        cudaGetSymbolAddress((void**)&el3b,  g_el3);
        cudaGetSymbolAddress((void**)&er3b,  g_er3);
        cudaGetSymbolAddress((void**)&w3mb,  g_W3m);
        cudaStreamCreateWithFlags(&s2, cudaStreamNonBlocking);
        cudaEventCreateWithFlags(&evFork, cudaEventDisableTiming);
        cudaEventCreateWithFlags(&evJoin, cudaEventDisableTiming);
    }

    const int TB = 256;
    const int nodeWarpGrid = (NN + 7) / 8;

    // ---- fork: CSR build + layer-3 prep on side stream ----
    cudaEventRecord(evFork, 0);
    cudaStreamWaitEvent(s2, evFork, 0);
    prep3_kernel<<<(128 * NP3 + TB - 1) / TB, TB, 0, s2>>>(W3, al3, ar3, b3);
    zero_deg_kernel<<<(NN + TB - 1) / TB, TB, 0, s2>>>();
    hist_kernel<<<(EE + TB - 1) / TB, TB, 0, s2>>>(dst);
    scan1_kernel<<<NBLK, TB, 0, s2>>>();
    scan2_kernel<<<1, 512, 0, s2>>>();
    scan3_kernel<<<NBLK, TB, 0, s2>>>();
    scatter_kernel<<<(EE + TB - 1) / TB, TB, 0, s2>>>(src, dst);
    cudaEventRecord(evJoin, s2);

    // ---- layer 1: gemm (+el/er) overlapped with CSR ----
    {
        dim3 gg((NN + BM - 1) / BM, 1);
        sgemm_kernel<128, true><<<gg, TB>>>(x, W1, featb, NN, 128, F_IN, al1, ar1);
    }
    cudaStreamWaitEvent(0, evJoin, 0);
    agg128_fused<true, false><<<nodeWarpGrid, TB>>>(featb, outb, elb, erb, b1);

    // ---- layer 2: gemm (+el/er), agg emits layer-3 logits ----
    {
        dim3 gg((NN + BM - 1) / BM, 1);
        sgemm_kernel<128, true><<<gg, TB>>>(outb, W2, featb, NN, 128, 128, al2, ar2);
        agg128_fused<true, true><<<nodeWarpGrid, TB>>>(featb, outb, elb, erb, b2);
    }
    // ---- layer 3: aggregate h (128-wide) then project through mean-folded W3m (N=48 padded) ----
    {
        agg128_fused<false, false><<<nodeWarpGrid, TB>>>(outb, featb, el3b, er3b, nullptr);
        dim3 gg((NN + BM - 1) / BM, 1);
        sgemm_kernel<64, false><<<gg, TB>>>(featb, w3mb, outb, NN, NP3, 128, nullptr, nullptr);
    }
    // ---- bias-mean + log_softmax ----
    final47_kernel<<<(NN + 7) / 8, TB>>>(y);
}